// round 6
// baseline (speedup 1.0000x reference)
#include <cuda_runtime.h>
#include <cuda_bf16.h>
#include <cstdint>

#define B_  2
#define T_  2048
#define D_  1024
#define F_  4096
#define H_  8
#define DH_ 128
#define M_  (B_*T_)              // 4096 rows
#define X_ELEMS (M_*D_)          // 4194304
#define QKV_N 3072

// ---------------- scratch (static device memory; no allocation at runtime) ----
static __device__ float g_xn [M_*D_];        // fp32 rmsnorm(x) (bgproj)
static __device__ float g_qkv[M_*QKV_N];     // fused q|k|v fp32
static __device__ float g_ba [M_*H_*2];

static __device__ __nv_bfloat16 g_xh[M_*D_], g_xl[M_*D_];    // A split (xn / yn)
static __device__ __nv_bfloat16 g_oh[M_*D_], g_ol[M_*D_];    // deltanet out split
static __device__ __nv_bfloat16 g_hh[M_*F_], g_hl[M_*F_];    // swiglu out split

static __device__ __nv_bfloat16 g_wqkvh[QKV_N*D_], g_wqkvl[QKV_N*D_];
static __device__ __nv_bfloat16 g_woh[D_*D_],      g_wol[D_*D_];
static __device__ __nv_bfloat16 g_wguh[2*F_*D_],   g_wgul[2*F_*D_];   // interleaved (g,u)
static __device__ __nv_bfloat16 g_wdh[D_*F_],      g_wdl[D_*F_];

__device__ __forceinline__ float silu_f(float x){ return x / (1.0f + expf(-x)); }
__device__ __forceinline__ float sigmoid_f(float x){ return 1.0f / (1.0f + expf(-x)); }

__device__ __forceinline__ uint32_t smem_u32(const void* p) {
    uint32_t a;
    asm("{ .reg .u64 t; cvta.to.shared.u64 t, %1; cvt.u32.u64 %0, t; }" : "=r"(a) : "l"(p));
    return a;
}
__device__ __forceinline__ void split2(float v, __nv_bfloat16& h, __nv_bfloat16& l) {
    h = __float2bfloat16(v);
    l = __float2bfloat16(v - __bfloat162float(h));
}

// ============================ elementwise / prep kernels ======================
// rmsnorm row of 1024 -> bf16 hi/lo (+ optional fp32)
__global__ __launch_bounds__(256) void rmsnorm_split_k(const float* __restrict__ in,
                                                       __nv_bfloat16* __restrict__ oh,
                                                       __nv_bfloat16* __restrict__ ol,
                                                       float* __restrict__ of)
{
    int row = blockIdx.x;
    int tid = threadIdx.x;
    const float4* ip = (const float4*)(in + (size_t)row * D_);
    float4 v = ip[tid];
    float ss = v.x*v.x + v.y*v.y + v.z*v.z + v.w*v.w;
    #pragma unroll
    for (int m = 16; m > 0; m >>= 1) ss += __shfl_xor_sync(0xffffffffu, ss, m);
    __shared__ float sred[8];
    if ((tid & 31) == 0) sred[tid >> 5] = ss;
    __syncthreads();
    float tot = 0.f;
    #pragma unroll
    for (int i = 0; i < 8; i++) tot += sred[i];
    float sc = rsqrtf(tot * (1.0f / D_) + 1e-6f);
    float4 o; o.x = v.x*sc; o.y = v.y*sc; o.z = v.z*sc; o.w = v.w*sc;
    __nv_bfloat16 h0,l0,h1,l1,h2,l2,h3,l3;
    split2(o.x,h0,l0); split2(o.y,h1,l1); split2(o.z,h2,l2); split2(o.w,h3,l3);
    __nv_bfloat162 hh0{h0,h1}, hh1{h2,h3}, ll0{l0,l1}, ll1{l2,l3};
    size_t base2 = ((size_t)row * D_) / 2 + tid*2;
    ((__nv_bfloat162*)oh)[base2]   = hh0;
    ((__nv_bfloat162*)oh)[base2+1] = hh1;
    ((__nv_bfloat162*)ol)[base2]   = ll0;
    ((__nv_bfloat162*)ol)[base2+1] = ll1;
    if (of) ((float4*)(of + (size_t)row * D_))[tid] = o;
}

// transpose [R][Cc] fp32 -> out[(c*cmul+cadd)][R] bf16 hi/lo
__global__ __launch_bounds__(256) void tsplit_k(const float* __restrict__ in,
                                                __nv_bfloat16* __restrict__ oh,
                                                __nv_bfloat16* __restrict__ ol,
                                                int R, int Cc, int cmul, int cadd)
{
    __shared__ float t[32][33];
    int tx = threadIdx.x & 31, ty = threadIdx.x >> 5;   // 32x8
    int c0 = blockIdx.x * 32, r0 = blockIdx.y * 32;
    #pragma unroll
    for (int i = 0; i < 4; i++)
        t[ty + i*8][tx] = in[(size_t)(r0 + ty + i*8) * Cc + c0 + tx];
    __syncthreads();
    #pragma unroll
    for (int i = 0; i < 4; i++) {
        int oc = ty + i*8;
        float v = t[tx][oc];
        __nv_bfloat16 h, l; split2(v, h, l);
        size_t oi = ((size_t)(c0 + oc) * cmul + cadd) * R + r0 + tx;
        oh[oi] = h; ol[oi] = l;
    }
}

// silu (+L2 norm for q,k heads) over fused qkv rows of 128
__global__ __launch_bounds__(256) void silul2_qkv_k(float* __restrict__ qkv)
{
    int r = blockIdx.x * 8 + (threadIdx.x >> 5);   // row-of-128 index, 0..M*24-1
    int lane = threadIdx.x & 31;
    int m = r / 24, sec = r % 24;
    float4* p = (float4*)(qkv + (size_t)m * QKV_N + sec * 128) + lane;
    float4 x = *p;
    float4 s;
    s.x = silu_f(x.x); s.y = silu_f(x.y); s.z = silu_f(x.z); s.w = silu_f(x.w);
    if (sec < 16) {   // q and k heads get L2 norm
        float ss = s.x*s.x + s.y*s.y + s.z*s.z + s.w*s.w;
        #pragma unroll
        for (int m2 = 16; m2 > 0; m2 >>= 1) ss += __shfl_xor_sync(0xffffffffu, ss, m2);
        float sc = rsqrtf(ss + 1e-6f);
        s.x *= sc; s.y *= sc; s.z *= sc; s.w *= sc;
    }
    *p = s;
}

// ============================ mma.sync split-bf16 GEMM ========================
// C[M,N] = (addend?) + A[M,K] @ Bt[N,K]^T  via 3-term bf16 split HMMA.
// Tile 128x128, BK=32, 256 threads (8 warps, warp tile 64x32), 3-stage cp.async.
// EPI: 0 = write C fp32; 1 = C = addend + acc; 2 = swiglu pairs -> bf16 hi/lo.
#define TILE_B (128*80)               // 10240 B per operand tile
#define STAGE_B (TILE_B*4)            // 40960 B per stage
#define HG_SMEM (STAGE_B*3)           // 122880 B

__device__ __forceinline__ void ldsm_x4(uint32_t& r0, uint32_t& r1,
                                        uint32_t& r2, uint32_t& r3, uint32_t a) {
    asm volatile("ldmatrix.sync.aligned.m8n8.x4.shared.b16 {%0,%1,%2,%3}, [%4];"
                 : "=r"(r0), "=r"(r1), "=r"(r2), "=r"(r3) : "r"(a));
}
__device__ __forceinline__ void mma16816(float& d0, float& d1, float& d2, float& d3,
                                         uint32_t a0, uint32_t a1, uint32_t a2, uint32_t a3,
                                         uint32_t b0, uint32_t b1) {
    asm volatile("mma.sync.aligned.m16n8k16.row.col.f32.bf16.bf16.f32 "
                 "{%0,%1,%2,%3}, {%4,%5,%6,%7}, {%8,%9}, {%0,%1,%2,%3};"
                 : "+f"(d0), "+f"(d1), "+f"(d2), "+f"(d3)
                 : "r"(a0), "r"(a1), "r"(a2), "r"(a3), "r"(b0), "r"(b1));
}
__device__ __forceinline__ void cp16(uint32_t s, const void* g) {
    asm volatile("cp.async.cg.shared.global [%0], [%1], 16;" :: "r"(s), "l"(g));
}

template<int EPI>
__global__ __launch_bounds__(256, 1) void hgemm_k(
    const __nv_bfloat16* __restrict__ Ah, const __nv_bfloat16* __restrict__ Al,
    const __nv_bfloat16* __restrict__ Bh, const __nv_bfloat16* __restrict__ Bl,
    const float* __restrict__ addend, float* __restrict__ C,
    __nv_bfloat16* __restrict__ Hh, __nv_bfloat16* __restrict__ Hl,
    int M, int N, int K)
{
    extern __shared__ char smem[];
    uint32_t S0 = smem_u32(smem);

    int tid = threadIdx.x;
    int wid = tid >> 5, lane = tid & 31;
    int m0 = blockIdx.y << 7, n0 = blockIdx.x << 7;

    int seg = tid & 3, rr = tid >> 2;
    const __nv_bfloat16* gA[4] = { Ah, Al, Bh, Bl };
    int rbase[4] = { m0, m0, n0, n0 };

    int NK = K >> 5;

    // prefetch stages 0,1
    #pragma unroll
    for (int st = 0; st < 2; st++) {
        uint32_t sb = S0 + st * STAGE_B;
        int k0 = st << 5;
        #pragma unroll
        for (int ten = 0; ten < 4; ten++) {
            const __nv_bfloat16* G = gA[ten] + (size_t)(rbase[ten] + rr) * K + k0 + seg * 8;
            uint32_t sa = sb + ten * TILE_B + rr * 80 + seg * 16;
            cp16(sa, G);
            cp16(sa + 64 * 80, G + (size_t)64 * K);
        }
        asm volatile("cp.async.commit_group;");
    }

    int wm = wid >> 2, wn = wid & 3;
    int m_off = wm * 64, n_off = wn * 32;

    uint32_t a_lo = (uint32_t)((lane & 15) * 80 + (lane >> 4) * 16);
    uint32_t b_lo = (uint32_t)(((lane & 7) + ((lane >> 4) << 3)) * 80 + (((lane >> 3) & 1) << 4));

    float acc[4][4][4];
    #pragma unroll
    for (int i = 0; i < 4; i++)
        #pragma unroll
        for (int j = 0; j < 4; j++)
            #pragma unroll
            for (int r = 0; r < 4; r++) acc[i][j][r] = 0.f;

    for (int kt = 0; kt < NK; kt++) {
        if (kt + 1 < NK) asm volatile("cp.async.wait_group 1;");
        else             asm volatile("cp.async.wait_group 0;");
        __syncthreads();

        if (kt + 2 < NK) {
            int st = (kt + 2) % 3;
            uint32_t sb = S0 + st * STAGE_B;
            int k0 = (kt + 2) << 5;
            #pragma unroll
            for (int ten = 0; ten < 4; ten++) {
                const __nv_bfloat16* G = gA[ten] + (size_t)(rbase[ten] + rr) * K + k0 + seg * 8;
                uint32_t sa = sb + ten * TILE_B + rr * 80 + seg * 16;
                cp16(sa, G);
                cp16(sa + 64 * 80, G + (size_t)64 * K);
            }
            asm volatile("cp.async.commit_group;");
        }

        uint32_t base = S0 + (kt % 3) * STAGE_B;
        uint32_t tAh = base, tAl = base + TILE_B, tBh = base + 2*TILE_B, tBl = base + 3*TILE_B;

        #pragma unroll
        for (int kk = 0; kk < 2; kk++) {
            uint32_t koff = (uint32_t)(kk * 32);
            uint32_t ah[4][4], al[4][4];
            #pragma unroll
            for (int mi = 0; mi < 4; mi++) {
                uint32_t off = (uint32_t)((m_off + mi*16) * 80) + koff + a_lo;
                ldsm_x4(ah[mi][0], ah[mi][1], ah[mi][2], ah[mi][3], tAh + off);
                ldsm_x4(al[mi][0], al[mi][1], al[mi][2], al[mi][3], tAl + off);
            }
            uint32_t bh[4][2], bl[4][2];
            #pragma unroll
            for (int ni = 0; ni < 2; ni++) {
                uint32_t off = (uint32_t)((n_off + ni*16) * 80) + koff + b_lo;
                uint32_t r0, r1, r2, r3;
                ldsm_x4(r0, r1, r2, r3, tBh + off);
                bh[ni*2][0] = r0; bh[ni*2][1] = r1; bh[ni*2+1][0] = r2; bh[ni*2+1][1] = r3;
                ldsm_x4(r0, r1, r2, r3, tBl + off);
                bl[ni*2][0] = r0; bl[ni*2][1] = r1; bl[ni*2+1][0] = r2; bl[ni*2+1][1] = r3;
            }
            #pragma unroll
            for (int mi = 0; mi < 4; mi++)
                #pragma unroll
                for (int ni = 0; ni < 4; ni++) {
                    mma16816(acc[mi][ni][0], acc[mi][ni][1], acc[mi][ni][2], acc[mi][ni][3],
                             ah[mi][0], ah[mi][1], ah[mi][2], ah[mi][3], bh[ni][0], bh[ni][1]);
                    mma16816(acc[mi][ni][0], acc[mi][ni][1], acc[mi][ni][2], acc[mi][ni][3],
                             ah[mi][0], ah[mi][1], ah[mi][2], ah[mi][3], bl[ni][0], bl[ni][1]);
                    mma16816(acc[mi][ni][0], acc[mi][ni][1], acc[mi][ni][2], acc[mi][ni][3],
                             al[mi][0], al[mi][1], al[mi][2], al[mi][3], bh[ni][0], bh[ni][1]);
                }
        }
        __syncthreads();
    }

    // epilogue
    int rbase_m = m0 + m_off + (lane >> 2);
    #pragma unroll
    for (int mi = 0; mi < 4; mi++) {
        #pragma unroll
        for (int ni = 0; ni < 4; ni++) {
            int row = rbase_m + mi * 16;
            if (EPI == 2) {
                // acc0 = gate(row), acc1 = up(row); acc2/acc3 same at row+8
                int c = n_off + ni*8 + (lane & 3) * 2;
                int j = (n0 + c) >> 1;
                int hw = N >> 1;
                float h1v = silu_f(acc[mi][ni][0]) * acc[mi][ni][1];
                float h2v = silu_f(acc[mi][ni][2]) * acc[mi][ni][3];
                __nv_bfloat16 h, l;
                split2(h1v, h, l);
                Hh[(size_t)row * hw + j] = h; Hl[(size_t)row * hw + j] = l;
                split2(h2v, h, l);
                Hh[(size_t)(row+8) * hw + j] = h; Hl[(size_t)(row+8) * hw + j] = l;
            } else {
                int col = n0 + n_off + ni*8 + (lane & 3) * 2;
                float2 v0 = { acc[mi][ni][0], acc[mi][ni][1] };
                float2 v1 = { acc[mi][ni][2], acc[mi][ni][3] };
                if (EPI == 1) {
                    float2 a0 = *(const float2*)(addend + (size_t)row * N + col);
                    float2 a1 = *(const float2*)(addend + (size_t)(row + 8) * N + col);
                    v0.x += a0.x; v0.y += a0.y; v1.x += a1.x; v1.y += a1.y;
                }
                *(float2*)(C + (size_t)row * N + col) = v0;
                *(float2*)(C + (size_t)(row + 8) * N + col) = v1;
            }
        }
    }
}

// ---------------- beta/alpha projection ---------------------------------------
__global__ __launch_bounds__(128) void bgproj_k(const float* __restrict__ xn,
                                                const float* __restrict__ wb,
                                                const float* __restrict__ wg,
                                                float* __restrict__ ba)
{
    int m = blockIdx.x;
    int tid = threadIdx.x;
    float accb[8], accg[8];
    #pragma unroll
    for (int j = 0; j < 8; j++) { accb[j] = 0.f; accg[j] = 0.f; }

    const float* xr = xn + (size_t)m * D_ + tid*8;
    #pragma unroll
    for (int u = 0; u < 8; u++) {
        float xv = xr[u];
        int krow = tid*8 + u;
        const float4* wbp = (const float4*)(wb + (size_t)krow * H_);
        const float4* wgp = (const float4*)(wg + (size_t)krow * H_);
        float4 b0 = wbp[0], b1 = wbp[1];
        float4 g0 = wgp[0], g1 = wgp[1];
        accb[0] += xv*b0.x; accb[1] += xv*b0.y; accb[2] += xv*b0.z; accb[3] += xv*b0.w;
        accb[4] += xv*b1.x; accb[5] += xv*b1.y; accb[6] += xv*b1.z; accb[7] += xv*b1.w;
        accg[0] += xv*g0.x; accg[1] += xv*g0.y; accg[2] += xv*g0.z; accg[3] += xv*g0.w;
        accg[4] += xv*g1.x; accg[5] += xv*g1.y; accg[6] += xv*g1.z; accg[7] += xv*g1.w;
    }
    __shared__ float red[16][128];
    #pragma unroll
    for (int j = 0; j < 8; j++) { red[j][tid] = accb[j]; red[8+j][tid] = accg[j]; }
    __syncthreads();
    if (tid < 16) {
        float s = 0.f;
        for (int i = 0; i < 128; i++) s += red[tid][i];
        float val = sigmoid_f(s);
        int h = tid & 7;
        int which = tid >> 3;
        ba[((size_t)m * H_ + h)*2 + which] = val;
    }
}

// ---------------- gated DeltaNet recurrence -----------------------------------
// Reads fused qkv (stride 3072); writes o directly as bf16 hi/lo.
__global__ __launch_bounds__(128) void deltarec_k(const float* __restrict__ qkv,
                                                  const float* __restrict__ ba,
                                                  const float* __restrict__ s0,
                                                  __nv_bfloat16* __restrict__ oh,
                                                  __nv_bfloat16* __restrict__ ol,
                                                  float* __restrict__ sout)
{
    int b = blockIdx.z, h = blockIdx.y, chunk = blockIdx.x;
    int tid = threadIdx.x;
    int warp = tid >> 5, lane = tid & 31;
    int grp = lane >> 4;
    int idx = lane & 15;
    int col = chunk*8 + warp*2 + grp;
    int r0  = idx * 8;

    float s[8];
    {
        const float* sp = s0 + (((size_t)(b*H_ + h)*DH_) + r0)*DH_ + col;
        #pragma unroll
        for (int i = 0; i < 8; i++) s[i] = sp[(size_t)i * DH_];
    }

    const float* base = qkv + (size_t)b * T_ * QKV_N + h * DH_;
    const float* qp  = base + r0;
    const float* kp  = base + 1024 + r0;
    const float* vp  = base + 2048 + col;
    const float* bap = ba + ((size_t)b * T_) * (H_*2) + h*2;
    size_t ooff = (size_t)b * T_ * D_ + (size_t)h * DH_ + col;

    float4 k0 = *(const float4*)(kp);
    float4 k1 = *(const float4*)(kp + 4);
    float4 q0 = *(const float4*)(qp);
    float4 q1 = *(const float4*)(qp + 4);
    float vv = *vp;
    float bb = bap[0];
    float aa = bap[1];

    for (int t = 0; t < T_; t++) {
        int tn = (t + 1 < T_) ? t + 1 : t;
        float4 nk0 = *(const float4*)(kp + (size_t)tn*QKV_N);
        float4 nk1 = *(const float4*)(kp + (size_t)tn*QKV_N + 4);
        float4 nq0 = *(const float4*)(qp + (size_t)tn*QKV_N);
        float4 nq1 = *(const float4*)(qp + (size_t)tn*QKV_N + 4);
        float nvv  = vp [(size_t)tn*QKV_N];
        float nbb  = bap[(size_t)tn*16];
        float naa  = bap[(size_t)tn*16 + 1];

        float kr[8] = {k0.x,k0.y,k0.z,k0.w,k1.x,k1.y,k1.z,k1.w};
        float qr[8] = {q0.x,q0.y,q0.z,q0.w,q1.x,q1.y,q1.z,q1.w};

        float pred = 0.f, po = 0.f, qk = 0.f;
        #pragma unroll
        for (int i = 0; i < 8; i++) {
            float sv = s[i] * aa;
            s[i] = sv;
            pred += kr[i] * sv;
            po   += qr[i] * sv;
            qk   += kr[i] * qr[i];
        }
        #pragma unroll
        for (int m = 1; m < 16; m <<= 1) {
            pred += __shfl_xor_sync(0xffffffffu, pred, m);
            po   += __shfl_xor_sync(0xffffffffu, po,   m);
            qk   += __shfl_xor_sync(0xffffffffu, qk,   m);
        }
        float dv = bb * (vv - pred);
        float ov = po + qk * dv;
        #pragma unroll
        for (int i = 0; i < 8; i++) s[i] += kr[i] * dv;

        if (idx == 0) {
            __nv_bfloat16 hh, ll; split2(ov, hh, ll);
            oh[ooff + (size_t)t*D_] = hh;
            ol[ooff + (size_t)t*D_] = ll;
        }

        k0 = nk0; k1 = nk1; q0 = nq0; q1 = nq1;
        vv = nvv; bb = nbb; aa = naa;
    }

    float* sp = sout + (((size_t)(b*H_ + h)*DH_) + r0)*DH_ + col;
    #pragma unroll
    for (int i = 0; i < 8; i++) sp[(size_t)i * DH_] = s[i];
}

// ---------------- launcher -----------------------------------------------------
struct Ptrs {
    float *xn, *qkv, *ba;
    __nv_bfloat16 *xh, *xl, *oh, *ol, *hh, *hl;
    __nv_bfloat16 *wqkvh, *wqkvl, *woh, *wol, *wguh, *wgul, *wdh, *wdl;
    bool init = false;
};
static Ptrs P;

extern "C" void kernel_launch(void* const* d_in, const int* in_sizes, int n_in,
                              void* d_out, int out_size)
{
    const float* x   = (const float*)d_in[0];
    const float* st0 = (const float*)d_in[1];
    const float* wq  = (const float*)d_in[2];
    const float* wk  = (const float*)d_in[3];
    const float* wv  = (const float*)d_in[4];
    const float* wb  = (const float*)d_in[5];
    const float* wg  = (const float*)d_in[6];
    const float* wo  = (const float*)d_in[7];
    const float* wgate = (const float*)d_in[8];
    const float* wup   = (const float*)d_in[9];
    const float* wdown = (const float*)d_in[10];

    float* out = (float*)d_out;   // [x (4194304) | new_state (262144)]
    float* y   = out;
    float* stO = out + X_ELEMS;

    if (!P.init) {
        cudaGetSymbolAddress((void**)&P.xn,  g_xn);
        cudaGetSymbolAddress((void**)&P.qkv, g_qkv);
        cudaGetSymbolAddress((void**)&P.ba,  g_ba);
        cudaGetSymbolAddress((void**)&P.xh,  g_xh);
        cudaGetSymbolAddress((void**)&P.xl,  g_xl);
        cudaGetSymbolAddress((void**)&P.oh,  g_oh);
        cudaGetSymbolAddress((void**)&P.ol,  g_ol);
        cudaGetSymbolAddress((void**)&P.hh,  g_hh);
        cudaGetSymbolAddress((void**)&P.hl,  g_hl);
        cudaGetSymbolAddress((void**)&P.wqkvh, g_wqkvh); cudaGetSymbolAddress((void**)&P.wqkvl, g_wqkvl);
        cudaGetSymbolAddress((void**)&P.woh,   g_woh);   cudaGetSymbolAddress((void**)&P.wol,   g_wol);
        cudaGetSymbolAddress((void**)&P.wguh,  g_wguh);  cudaGetSymbolAddress((void**)&P.wgul,  g_wgul);
        cudaGetSymbolAddress((void**)&P.wdh,   g_wdh);   cudaGetSymbolAddress((void**)&P.wdl,   g_wdl);
        cudaFuncSetAttribute(hgemm_k<0>, cudaFuncAttributeMaxDynamicSharedMemorySize, HG_SMEM);
        cudaFuncSetAttribute(hgemm_k<1>, cudaFuncAttributeMaxDynamicSharedMemorySize, HG_SMEM);
        cudaFuncSetAttribute(hgemm_k<2>, cudaFuncAttributeMaxDynamicSharedMemorySize, HG_SMEM);
        P.init = true;
    }

    // weight transposes + bf16 splits
    tsplit_k<<<dim3(D_/32, D_/32), 256>>>(wq, P.wqkvh, P.wqkvl, D_, D_, 1, 0);
    tsplit_k<<<dim3(D_/32, D_/32), 256>>>(wk, P.wqkvh, P.wqkvl, D_, D_, 1, 1024);
    tsplit_k<<<dim3(D_/32, D_/32), 256>>>(wv, P.wqkvh, P.wqkvl, D_, D_, 1, 2048);
    tsplit_k<<<dim3(D_/32, D_/32), 256>>>(wo, P.woh,   P.wol,   D_, D_, 1, 0);
    tsplit_k<<<dim3(F_/32, D_/32), 256>>>(wgate, P.wguh, P.wgul, D_, F_, 2, 0);
    tsplit_k<<<dim3(F_/32, D_/32), 256>>>(wup,   P.wguh, P.wgul, D_, F_, 2, 1);
    tsplit_k<<<dim3(D_/32, F_/32), 256>>>(wdown, P.wdh,  P.wdl,  F_, D_, 1, 0);

    // 1) xn = rmsnorm(x) -> hi/lo + fp32 (for bgproj)
    rmsnorm_split_k<<<M_, 256>>>(x, P.xh, P.xl, P.xn);

    // 2) fused qkv projection + gates
    hgemm_k<0><<<dim3(QKV_N/128, M_/128), 256, HG_SMEM>>>(
        P.xh, P.xl, P.wqkvh, P.wqkvl, nullptr, P.qkv, nullptr, nullptr, M_, QKV_N, D_);
    bgproj_k<<<M_, 128>>>(P.xn, wb, wg, P.ba);

    // 3) silu + per-head L2 norm (q,k); silu (v) — fused over qkv
    silul2_qkv_k<<<(M_*24)/8, 256>>>(P.qkv);

    // 4) recurrence -> o (bf16 split), final state
    deltarec_k<<<dim3(16, H_, B_), 128>>>(P.qkv, P.ba, st0, P.oh, P.ol, stO);

    // 5) y = x + o @ wo
    hgemm_k<1><<<dim3(D_/128, M_/128), 256, HG_SMEM>>>(
        P.oh, P.ol, P.woh, P.wol, x, y, nullptr, nullptr, M_, D_, D_);

    // 6) yn = rmsnorm(y) -> hi/lo; fused gate/up GEMM with swiglu epilogue
    rmsnorm_split_k<<<M_, 256>>>(y, P.xh, P.xl, nullptr);
    hgemm_k<2><<<dim3(2*F_/128, M_/128), 256, HG_SMEM>>>(
        P.xh, P.xl, P.wguh, P.wgul, nullptr, nullptr, P.hh, P.hl, M_, 2*F_, D_);

    // 7) out = y + h @ w_down
    hgemm_k<1><<<dim3(D_/128, M_/128), 256, HG_SMEM>>>(
        P.hh, P.hl, P.wdh, P.wdl, y, y, nullptr, nullptr, M_, D_, F_);
}

// round 7
// speedup vs baseline: 1.5121x; 1.5121x over previous
#include <cuda_runtime.h>
#include <cuda_fp16.h>
#include <cstdint>

#define B_  2
#define T_  2048
#define D_  1024
#define F_  4096
#define H_  8
#define DH_ 128
#define M_  (B_*T_)              // 4096 rows
#define X_ELEMS (M_*D_)          // 4194304
#define QKV_N 3072

// ---------------- scratch (static device memory; no allocation at runtime) ----
static __device__ float g_xn [M_*D_];        // fp32 rmsnorm(x) (bgproj)
static __device__ float g_qkv[M_*QKV_N];     // fused q|k|v fp32
static __device__ float g_ba [M_*H_*2];

static __device__ __half g_xh[M_*D_];        // A operand fp16 (xn / yn)
static __device__ __half g_oh[M_*D_];        // deltanet out fp16
static __device__ __half g_hh[M_*F_];        // swiglu out fp16

static __device__ __half g_wqkv[QKV_N*D_];
static __device__ __half g_wo  [D_*D_];
static __device__ __half g_wgu [2*F_*D_];    // interleaved (gate,up) columns
static __device__ __half g_wd  [D_*F_];

__device__ __forceinline__ float silu_f(float x){ return x / (1.0f + expf(-x)); }
__device__ __forceinline__ float sigmoid_f(float x){ return 1.0f / (1.0f + expf(-x)); }

__device__ __forceinline__ uint32_t smem_u32(const void* p) {
    uint32_t a;
    asm("{ .reg .u64 t; cvta.to.shared.u64 t, %1; cvt.u32.u64 %0, t; }" : "=r"(a) : "l"(p));
    return a;
}

// ============================ elementwise / prep kernels ======================
// rmsnorm row of 1024 -> fp16 (+ optional fp32)
__global__ __launch_bounds__(256) void rmsnorm_h_k(const float* __restrict__ in,
                                                   __half* __restrict__ oh,
                                                   float* __restrict__ of)
{
    int row = blockIdx.x;
    int tid = threadIdx.x;
    const float4* ip = (const float4*)(in + (size_t)row * D_);
    float4 v = ip[tid];
    float ss = v.x*v.x + v.y*v.y + v.z*v.z + v.w*v.w;
    #pragma unroll
    for (int m = 16; m > 0; m >>= 1) ss += __shfl_xor_sync(0xffffffffu, ss, m);
    __shared__ float sred[8];
    if ((tid & 31) == 0) sred[tid >> 5] = ss;
    __syncthreads();
    float tot = 0.f;
    #pragma unroll
    for (int i = 0; i < 8; i++) tot += sred[i];
    float sc = rsqrtf(tot * (1.0f / D_) + 1e-6f);
    float4 o; o.x = v.x*sc; o.y = v.y*sc; o.z = v.z*sc; o.w = v.w*sc;
    __half2 h0 = __floats2half2_rn(o.x, o.y);
    __half2 h1 = __floats2half2_rn(o.z, o.w);
    size_t base2 = ((size_t)row * D_) / 2 + tid*2;
    ((__half2*)oh)[base2]   = h0;
    ((__half2*)oh)[base2+1] = h1;
    if (of) ((float4*)(of + (size_t)row * D_))[tid] = o;
}

// transpose [R][Cc] fp32 -> out[(c*cmul+cadd)][R] fp16
__global__ __launch_bounds__(256) void tsplit_k(const float* __restrict__ in,
                                                __half* __restrict__ oh,
                                                int R, int Cc, int cmul, int cadd)
{
    __shared__ float t[32][33];
    int tx = threadIdx.x & 31, ty = threadIdx.x >> 5;   // 32x8
    int c0 = blockIdx.x * 32, r0 = blockIdx.y * 32;
    #pragma unroll
    for (int i = 0; i < 4; i++)
        t[ty + i*8][tx] = in[(size_t)(r0 + ty + i*8) * Cc + c0 + tx];
    __syncthreads();
    #pragma unroll
    for (int i = 0; i < 4; i++) {
        int oc = ty + i*8;
        size_t oi = ((size_t)(c0 + oc) * cmul + cadd) * R + r0 + tx;
        oh[oi] = __float2half(t[tx][oc]);
    }
}

// silu (+L2 norm for q,k heads) over fused qkv rows of 128
__global__ __launch_bounds__(256) void silul2_qkv_k(float* __restrict__ qkv)
{
    int r = blockIdx.x * 8 + (threadIdx.x >> 5);   // row-of-128 index, 0..M*24-1
    int lane = threadIdx.x & 31;
    int m = r / 24, sec = r % 24;
    float4* p = (float4*)(qkv + (size_t)m * QKV_N + sec * 128) + lane;
    float4 x = *p;
    float4 s;
    s.x = silu_f(x.x); s.y = silu_f(x.y); s.z = silu_f(x.z); s.w = silu_f(x.w);
    if (sec < 16) {   // q and k heads get L2 norm
        float ss = s.x*s.x + s.y*s.y + s.z*s.z + s.w*s.w;
        #pragma unroll
        for (int m2 = 16; m2 > 0; m2 >>= 1) ss += __shfl_xor_sync(0xffffffffu, ss, m2);
        float sc = rsqrtf(ss + 1e-6f);
        s.x *= sc; s.y *= sc; s.z *= sc; s.w *= sc;
    }
    *p = s;
}

// ============================ mma.sync fp16 GEMM ==============================
// C[M,N] = (addend?) + A[M,K] @ Bt[N,K]^T, fp16 in, fp32 accumulate.
// Tile 128x128, BK=32, 256 threads (8 warps, warp tile 64x32), 4-stage cp.async.
// EPI: 0 = write C fp32; 1 = C = addend + acc; 2 = swiglu pairs -> fp16.
#define TILE_B (128*80)               // 10240 B per operand tile
#define STAGE_B (TILE_B*2)            // 20480 B per stage (A,B)
#define HG_SMEM (STAGE_B*4)           // 81920 B

__device__ __forceinline__ void ldsm_x4(uint32_t& r0, uint32_t& r1,
                                        uint32_t& r2, uint32_t& r3, uint32_t a) {
    asm volatile("ldmatrix.sync.aligned.m8n8.x4.shared.b16 {%0,%1,%2,%3}, [%4];"
                 : "=r"(r0), "=r"(r1), "=r"(r2), "=r"(r3) : "r"(a));
}
__device__ __forceinline__ void mma16816(float& d0, float& d1, float& d2, float& d3,
                                         uint32_t a0, uint32_t a1, uint32_t a2, uint32_t a3,
                                         uint32_t b0, uint32_t b1) {
    asm volatile("mma.sync.aligned.m16n8k16.row.col.f32.f16.f16.f32 "
                 "{%0,%1,%2,%3}, {%4,%5,%6,%7}, {%8,%9}, {%0,%1,%2,%3};"
                 : "+f"(d0), "+f"(d1), "+f"(d2), "+f"(d3)
                 : "r"(a0), "r"(a1), "r"(a2), "r"(a3), "r"(b0), "r"(b1));
}
__device__ __forceinline__ void cp16(uint32_t s, const void* g) {
    asm volatile("cp.async.cg.shared.global [%0], [%1], 16;" :: "r"(s), "l"(g));
}

template<int EPI>
__global__ __launch_bounds__(256, 1) void hgemm_k(
    const __half* __restrict__ Ah, const __half* __restrict__ Bh,
    const float* __restrict__ addend, float* __restrict__ C,
    __half* __restrict__ Hh,
    int M, int N, int K)
{
    extern __shared__ char smem[];
    uint32_t S0 = smem_u32(smem);

    int tid = threadIdx.x;
    int wid = tid >> 5, lane = tid & 31;
    int m0 = blockIdx.y << 7, n0 = blockIdx.x << 7;

    int seg = tid & 3, rr = tid >> 2;
    const __half* gA[2] = { Ah, Bh };
    int rbase[2] = { m0, n0 };

    int NK = K >> 5;

    // prefetch stages 0..2
    #pragma unroll
    for (int st = 0; st < 3; st++) {
        uint32_t sb = S0 + st * STAGE_B;
        int k0 = st << 5;
        #pragma unroll
        for (int ten = 0; ten < 2; ten++) {
            const __half* G = gA[ten] + (size_t)(rbase[ten] + rr) * K + k0 + seg * 8;
            uint32_t sa = sb + ten * TILE_B + rr * 80 + seg * 16;
            cp16(sa, G);
            cp16(sa + 64 * 80, G + (size_t)64 * K);
        }
        asm volatile("cp.async.commit_group;");
    }

    int wm = wid >> 2, wn = wid & 3;
    int m_off = wm * 64, n_off = wn * 32;

    uint32_t a_lo = (uint32_t)((lane & 15) * 80 + (lane >> 4) * 16);
    uint32_t b_lo = (uint32_t)(((lane & 7) + ((lane >> 4) << 3)) * 80 + (((lane >> 3) & 1) << 4));

    float acc[4][4][4];
    #pragma unroll
    for (int i = 0; i < 4; i++)
        #pragma unroll
        for (int j = 0; j < 4; j++)
            #pragma unroll
            for (int r = 0; r < 4; r++) acc[i][j][r] = 0.f;

    for (int kt = 0; kt < NK; kt++) {
        if      (kt + 2 < NK) asm volatile("cp.async.wait_group 2;");
        else if (kt + 1 < NK) asm volatile("cp.async.wait_group 1;");
        else                  asm volatile("cp.async.wait_group 0;");
        __syncthreads();

        if (kt + 3 < NK) {
            int st = (kt + 3) & 3;
            uint32_t sb = S0 + st * STAGE_B;
            int k0 = (kt + 3) << 5;
            #pragma unroll
            for (int ten = 0; ten < 2; ten++) {
                const __half* G = gA[ten] + (size_t)(rbase[ten] + rr) * K + k0 + seg * 8;
                uint32_t sa = sb + ten * TILE_B + rr * 80 + seg * 16;
                cp16(sa, G);
                cp16(sa + 64 * 80, G + (size_t)64 * K);
            }
            asm volatile("cp.async.commit_group;");
        }

        uint32_t base = S0 + (kt & 3) * STAGE_B;
        uint32_t tA = base, tB = base + TILE_B;

        #pragma unroll
        for (int kk = 0; kk < 2; kk++) {
            uint32_t koff = (uint32_t)(kk * 32);
            uint32_t ah[4][4];
            #pragma unroll
            for (int mi = 0; mi < 4; mi++) {
                uint32_t off = (uint32_t)((m_off + mi*16) * 80) + koff + a_lo;
                ldsm_x4(ah[mi][0], ah[mi][1], ah[mi][2], ah[mi][3], tA + off);
            }
            uint32_t bh[4][2];
            #pragma unroll
            for (int ni = 0; ni < 2; ni++) {
                uint32_t off = (uint32_t)((n_off + ni*16) * 80) + koff + b_lo;
                uint32_t r0, r1, r2, r3;
                ldsm_x4(r0, r1, r2, r3, tB + off);
                bh[ni*2][0] = r0; bh[ni*2][1] = r1; bh[ni*2+1][0] = r2; bh[ni*2+1][1] = r3;
            }
            #pragma unroll
            for (int mi = 0; mi < 4; mi++)
                #pragma unroll
                for (int ni = 0; ni < 4; ni++)
                    mma16816(acc[mi][ni][0], acc[mi][ni][1], acc[mi][ni][2], acc[mi][ni][3],
                             ah[mi][0], ah[mi][1], ah[mi][2], ah[mi][3], bh[ni][0], bh[ni][1]);
        }
        __syncthreads();
    }

    // epilogue
    int rbase_m = m0 + m_off + (lane >> 2);
    #pragma unroll
    for (int mi = 0; mi < 4; mi++) {
        #pragma unroll
        for (int ni = 0; ni < 4; ni++) {
            int row = rbase_m + mi * 16;
            if (EPI == 2) {
                // acc0 = gate(row), acc1 = up(row); acc2/acc3 same at row+8
                int c = n_off + ni*8 + (lane & 3) * 2;
                int j = (n0 + c) >> 1;
                int hw = N >> 1;
                float h1v = silu_f(acc[mi][ni][0]) * acc[mi][ni][1];
                float h2v = silu_f(acc[mi][ni][2]) * acc[mi][ni][3];
                Hh[(size_t)row * hw + j]     = __float2half(h1v);
                Hh[(size_t)(row+8) * hw + j] = __float2half(h2v);
            } else {
                int col = n0 + n_off + ni*8 + (lane & 3) * 2;
                float2 v0 = { acc[mi][ni][0], acc[mi][ni][1] };
                float2 v1 = { acc[mi][ni][2], acc[mi][ni][3] };
                if (EPI == 1) {
                    float2 a0 = *(const float2*)(addend + (size_t)row * N + col);
                    float2 a1 = *(const float2*)(addend + (size_t)(row + 8) * N + col);
                    v0.x += a0.x; v0.y += a0.y; v1.x += a1.x; v1.y += a1.y;
                }
                *(float2*)(C + (size_t)row * N + col) = v0;
                *(float2*)(C + (size_t)(row + 8) * N + col) = v1;
            }
        }
    }
}

// ---------------- beta/alpha projection ---------------------------------------
__global__ __launch_bounds__(128) void bgproj_k(const float* __restrict__ xn,
                                                const float* __restrict__ wb,
                                                const float* __restrict__ wg,
                                                float* __restrict__ ba)
{
    int m = blockIdx.x;
    int tid = threadIdx.x;
    float accb[8], accg[8];
    #pragma unroll
    for (int j = 0; j < 8; j++) { accb[j] = 0.f; accg[j] = 0.f; }

    const float* xr = xn + (size_t)m * D_ + tid*8;
    #pragma unroll
    for (int u = 0; u < 8; u++) {
        float xv = xr[u];
        int krow = tid*8 + u;
        const float4* wbp = (const float4*)(wb + (size_t)krow * H_);
        const float4* wgp = (const float4*)(wg + (size_t)krow * H_);
        float4 b0 = wbp[0], b1 = wbp[1];
        float4 g0 = wgp[0], g1 = wgp[1];
        accb[0] += xv*b0.x; accb[1] += xv*b0.y; accb[2] += xv*b0.z; accb[3] += xv*b0.w;
        accb[4] += xv*b1.x; accb[5] += xv*b1.y; accb[6] += xv*b1.z; accb[7] += xv*b1.w;
        accg[0] += xv*g0.x; accg[1] += xv*g0.y; accg[2] += xv*g0.z; accg[3] += xv*g0.w;
        accg[4] += xv*g1.x; accg[5] += xv*g1.y; accg[6] += xv*g1.z; accg[7] += xv*g1.w;
    }
    __shared__ float red[16][128];
    #pragma unroll
    for (int j = 0; j < 8; j++) { red[j][tid] = accb[j]; red[8+j][tid] = accg[j]; }
    __syncthreads();
    if (tid < 16) {
        float s = 0.f;
        for (int i = 0; i < 128; i++) s += red[tid][i];
        float val = sigmoid_f(s);
        int h = tid & 7;
        int which = tid >> 3;
        ba[((size_t)m * H_ + h)*2 + which] = val;
    }
}

// ---------------- gated DeltaNet recurrence -----------------------------------
// Reads fused qkv (stride 3072); writes o directly as fp16.
__global__ __launch_bounds__(128) void deltarec_k(const float* __restrict__ qkv,
                                                  const float* __restrict__ ba,
                                                  const float* __restrict__ s0,
                                                  __half* __restrict__ oh,
                                                  float* __restrict__ sout)
{
    int b = blockIdx.z, h = blockIdx.y, chunk = blockIdx.x;
    int tid = threadIdx.x;
    int warp = tid >> 5, lane = tid & 31;
    int grp = lane >> 4;
    int idx = lane & 15;
    int col = chunk*8 + warp*2 + grp;
    int r0  = idx * 8;

    float s[8];
    {
        const float* sp = s0 + (((size_t)(b*H_ + h)*DH_) + r0)*DH_ + col;
        #pragma unroll
        for (int i = 0; i < 8; i++) s[i] = sp[(size_t)i * DH_];
    }

    const float* base = qkv + (size_t)b * T_ * QKV_N + h * DH_;
    const float* qp  = base + r0;
    const float* kp  = base + 1024 + r0;
    const float* vp  = base + 2048 + col;
    const float* bap = ba + ((size_t)b * T_) * (H_*2) + h*2;
    size_t ooff = (size_t)b * T_ * D_ + (size_t)h * DH_ + col;

    float4 k0 = *(const float4*)(kp);
    float4 k1 = *(const float4*)(kp + 4);
    float4 q0 = *(const float4*)(qp);
    float4 q1 = *(const float4*)(qp + 4);
    float vv = *vp;
    float bb = bap[0];
    float aa = bap[1];

    for (int t = 0; t < T_; t++) {
        int tn = (t + 1 < T_) ? t + 1 : t;
        float4 nk0 = *(const float4*)(kp + (size_t)tn*QKV_N);
        float4 nk1 = *(const float4*)(kp + (size_t)tn*QKV_N + 4);
        float4 nq0 = *(const float4*)(qp + (size_t)tn*QKV_N);
        float4 nq1 = *(const float4*)(qp + (size_t)tn*QKV_N + 4);
        float nvv  = vp [(size_t)tn*QKV_N];
        float nbb  = bap[(size_t)tn*16];
        float naa  = bap[(size_t)tn*16 + 1];

        float kr[8] = {k0.x,k0.y,k0.z,k0.w,k1.x,k1.y,k1.z,k1.w};
        float qr[8] = {q0.x,q0.y,q0.z,q0.w,q1.x,q1.y,q1.z,q1.w};

        float pred = 0.f, po = 0.f, qk = 0.f;
        #pragma unroll
        for (int i = 0; i < 8; i++) {
            float sv = s[i] * aa;
            s[i] = sv;
            pred += kr[i] * sv;
            po   += qr[i] * sv;
            qk   += kr[i] * qr[i];
        }
        #pragma unroll
        for (int m = 1; m < 16; m <<= 1) {
            pred += __shfl_xor_sync(0xffffffffu, pred, m);
            po   += __shfl_xor_sync(0xffffffffu, po,   m);
            qk   += __shfl_xor_sync(0xffffffffu, qk,   m);
        }
        float dv = bb * (vv - pred);
        float ov = po + qk * dv;
        #pragma unroll
        for (int i = 0; i < 8; i++) s[i] += kr[i] * dv;

        if (idx == 0) oh[ooff + (size_t)t*D_] = __float2half(ov);

        k0 = nk0; k1 = nk1; q0 = nq0; q1 = nq1;
        vv = nvv; bb = nbb; aa = naa;
    }

    float* sp = sout + (((size_t)(b*H_ + h)*DH_) + r0)*DH_ + col;
    #pragma unroll
    for (int i = 0; i < 8; i++) sp[(size_t)i * DH_] = s[i];
}

// ---------------- launcher -----------------------------------------------------
struct Ptrs {
    float *xn, *qkv, *ba;
    __half *xh, *oh, *hh;
    __half *wqkv, *wo, *wgu, *wd;
    bool init = false;
};
static Ptrs P;

extern "C" void kernel_launch(void* const* d_in, const int* in_sizes, int n_in,
                              void* d_out, int out_size)
{
    const float* x   = (const float*)d_in[0];
    const float* st0 = (const float*)d_in[1];
    const float* wq  = (const float*)d_in[2];
    const float* wk  = (const float*)d_in[3];
    const float* wv  = (const float*)d_in[4];
    const float* wb  = (const float*)d_in[5];
    const float* wg  = (const float*)d_in[6];
    const float* wo  = (const float*)d_in[7];
    const float* wgate = (const float*)d_in[8];
    const float* wup   = (const float*)d_in[9];
    const float* wdown = (const float*)d_in[10];

    float* out = (float*)d_out;   // [x (4194304) | new_state (262144)]
    float* y   = out;
    float* stO = out + X_ELEMS;

    if (!P.init) {
        cudaGetSymbolAddress((void**)&P.xn,  g_xn);
        cudaGetSymbolAddress((void**)&P.qkv, g_qkv);
        cudaGetSymbolAddress((void**)&P.ba,  g_ba);
        cudaGetSymbolAddress((void**)&P.xh,  g_xh);
        cudaGetSymbolAddress((void**)&P.oh,  g_oh);
        cudaGetSymbolAddress((void**)&P.hh,  g_hh);
        cudaGetSymbolAddress((void**)&P.wqkv, g_wqkv);
        cudaGetSymbolAddress((void**)&P.wo,   g_wo);
        cudaGetSymbolAddress((void**)&P.wgu,  g_wgu);
        cudaGetSymbolAddress((void**)&P.wd,   g_wd);
        cudaFuncSetAttribute(hgemm_k<0>, cudaFuncAttributeMaxDynamicSharedMemorySize, HG_SMEM);
        cudaFuncSetAttribute(hgemm_k<1>, cudaFuncAttributeMaxDynamicSharedMemorySize, HG_SMEM);
        cudaFuncSetAttribute(hgemm_k<2>, cudaFuncAttributeMaxDynamicSharedMemorySize, HG_SMEM);
        P.init = true;
    }

    // weight transposes -> fp16 [N][K]
    tsplit_k<<<dim3(D_/32, D_/32), 256>>>(wq, P.wqkv, D_, D_, 1, 0);
    tsplit_k<<<dim3(D_/32, D_/32), 256>>>(wk, P.wqkv, D_, D_, 1, 1024);
    tsplit_k<<<dim3(D_/32, D_/32), 256>>>(wv, P.wqkv, D_, D_, 1, 2048);
    tsplit_k<<<dim3(D_/32, D_/32), 256>>>(wo, P.wo,   D_, D_, 1, 0);
    tsplit_k<<<dim3(F_/32, D_/32), 256>>>(wgate, P.wgu, D_, F_, 2, 0);
    tsplit_k<<<dim3(F_/32, D_/32), 256>>>(wup,   P.wgu, D_, F_, 2, 1);
    tsplit_k<<<dim3(D_/32, F_/32), 256>>>(wdown, P.wd,  F_, D_, 1, 0);

    // 1) xn = rmsnorm(x) -> fp16 + fp32 (for bgproj)
    rmsnorm_h_k<<<M_, 256>>>(x, P.xh, P.xn);

    // 2) fused qkv projection + gates
    hgemm_k<0><<<dim3(QKV_N/128, M_/128), 256, HG_SMEM>>>(
        P.xh, P.wqkv, nullptr, P.qkv, nullptr, M_, QKV_N, D_);
    bgproj_k<<<M_, 128>>>(P.xn, wb, wg, P.ba);

    // 3) silu + per-head L2 norm (q,k); silu (v) — fused over qkv
    silul2_qkv_k<<<(M_*24)/8, 256>>>(P.qkv);

    // 4) recurrence -> o (fp16), final state
    deltarec_k<<<dim3(16, H_, B_), 128>>>(P.qkv, P.ba, st0, P.oh, stO);

    // 5) y = x + o @ wo
    hgemm_k<1><<<dim3(D_/128, M_/128), 256, HG_SMEM>>>(
        P.oh, P.wo, x, y, nullptr, M_, D_, D_);

    // 6) yn = rmsnorm(y) -> fp16; fused gate/up GEMM with swiglu epilogue
    rmsnorm_h_k<<<M_, 256>>>(y, P.xh, nullptr);
    hgemm_k<2><<<dim3(2*F_/128, M_/128), 256, HG_SMEM>>>(
        P.xh, P.wgu, nullptr, nullptr, P.hh, M_, 2*F_, D_);

    // 7) out = y + h @ w_down
    hgemm_k<1><<<dim3(D_/128, M_/128), 256, HG_SMEM>>>(
        P.hh, P.wd, y, y, nullptr, M_, D_, F_);
}

// round 8
// speedup vs baseline: 1.7216x; 1.1385x over previous
#include <cuda_runtime.h>
#include <cuda_fp16.h>
#include <cstdint>

#define B_  2
#define T_  2048
#define D_  1024
#define F_  4096
#define H_  8
#define DH_ 128
#define M_  (B_*T_)              // 4096 rows
#define X_ELEMS (M_*D_)          // 4194304
#define QKV_N 3072

// ---------------- scratch (static device memory; no allocation at runtime) ----
static __device__ float g_xn [M_*D_];        // fp32 rmsnorm(x) (bgproj)
static __device__ float g_qkv[M_*QKV_N];     // fused q|k|v fp32
static __device__ float g_ba [M_*H_*2];

static __device__ __half g_xh[M_*D_];        // A operand fp16 (xn / yn)
static __device__ __half g_oh[M_*D_];        // deltanet out fp16
static __device__ __half g_hh[M_*F_];        // swiglu out fp16

static __device__ __half g_wqkv[QKV_N*D_];
static __device__ __half g_wo  [D_*D_];
static __device__ __half g_wgu [2*F_*D_];    // interleaved (gate,up) columns
static __device__ __half g_wd  [D_*F_];

__device__ __forceinline__ float silu_f(float x){ return x / (1.0f + expf(-x)); }
__device__ __forceinline__ float sigmoid_f(float x){ return 1.0f / (1.0f + expf(-x)); }

__device__ __forceinline__ uint32_t smem_u32(const void* p) {
    uint32_t a;
    asm("{ .reg .u64 t; cvta.to.shared.u64 t, %1; cvt.u32.u64 %0, t; }" : "=r"(a) : "l"(p));
    return a;
}

// ============================ elementwise / prep kernels ======================
// rmsnorm row of 1024 -> fp16 (+ optional fp32)
__global__ __launch_bounds__(256) void rmsnorm_h_k(const float* __restrict__ in,
                                                   __half* __restrict__ oh,
                                                   float* __restrict__ of)
{
    int row = blockIdx.x;
    int tid = threadIdx.x;
    const float4* ip = (const float4*)(in + (size_t)row * D_);
    float4 v = ip[tid];
    float ss = v.x*v.x + v.y*v.y + v.z*v.z + v.w*v.w;
    #pragma unroll
    for (int m = 16; m > 0; m >>= 1) ss += __shfl_xor_sync(0xffffffffu, ss, m);
    __shared__ float sred[8];
    if ((tid & 31) == 0) sred[tid >> 5] = ss;
    __syncthreads();
    float tot = 0.f;
    #pragma unroll
    for (int i = 0; i < 8; i++) tot += sred[i];
    float sc = rsqrtf(tot * (1.0f / D_) + 1e-6f);
    float4 o; o.x = v.x*sc; o.y = v.y*sc; o.z = v.z*sc; o.w = v.w*sc;
    __half2 h0 = __floats2half2_rn(o.x, o.y);
    __half2 h1 = __floats2half2_rn(o.z, o.w);
    size_t base2 = ((size_t)row * D_) / 2 + tid*2;
    ((__half2*)oh)[base2]   = h0;
    ((__half2*)oh)[base2+1] = h1;
    if (of) ((float4*)(of + (size_t)row * D_))[tid] = o;
}

// transpose [R][Cc] fp32 -> out[(c*cmul+cadd)][R] fp16
__global__ __launch_bounds__(256) void tsplit_k(const float* __restrict__ in,
                                                __half* __restrict__ oh,
                                                int R, int Cc, int cmul, int cadd)
{
    __shared__ float t[32][33];
    int tx = threadIdx.x & 31, ty = threadIdx.x >> 5;   // 32x8
    int c0 = blockIdx.x * 32, r0 = blockIdx.y * 32;
    #pragma unroll
    for (int i = 0; i < 4; i++)
        t[ty + i*8][tx] = in[(size_t)(r0 + ty + i*8) * Cc + c0 + tx];
    __syncthreads();
    #pragma unroll
    for (int i = 0; i < 4; i++) {
        int oc = ty + i*8;
        size_t oi = ((size_t)(c0 + oc) * cmul + cadd) * R + r0 + tx;
        oh[oi] = __float2half(t[tx][oc]);
    }
}

// silu (+L2 norm for q,k heads) over fused qkv rows of 128
__global__ __launch_bounds__(256) void silul2_qkv_k(float* __restrict__ qkv)
{
    int r = blockIdx.x * 8 + (threadIdx.x >> 5);   // row-of-128 index, 0..M*24-1
    int lane = threadIdx.x & 31;
    int m = r / 24, sec = r % 24;
    float4* p = (float4*)(qkv + (size_t)m * QKV_N + sec * 128) + lane;
    float4 x = *p;
    float4 s;
    s.x = silu_f(x.x); s.y = silu_f(x.y); s.z = silu_f(x.z); s.w = silu_f(x.w);
    if (sec < 16) {   // q and k heads get L2 norm
        float ss = s.x*s.x + s.y*s.y + s.z*s.z + s.w*s.w;
        #pragma unroll
        for (int m2 = 16; m2 > 0; m2 >>= 1) ss += __shfl_xor_sync(0xffffffffu, ss, m2);
        float sc = rsqrtf(ss + 1e-6f);
        s.x *= sc; s.y *= sc; s.z *= sc; s.w *= sc;
    }
    *p = s;
}

// ============================ mma.sync fp16 GEMM ==============================
// C[M,N] = (addend?) + A[M,K] @ Bt[N,K]^T, fp16 in, fp32 accumulate.
// Tile 128x128, BK=32, 128 threads (4 warps, warp tile 64x64), 4-stage cp.async,
// 2 CTAs/SM.  EPI: 0 = write C fp32; 1 = C = addend + acc; 2 = swiglu -> fp16.
#define TILE_B (128*80)               // 10240 B per operand tile
#define STAGE_B (TILE_B*2)            // 20480 B per stage (A,B)
#define HG_SMEM (STAGE_B*4)           // 81920 B

__device__ __forceinline__ void ldsm_x4(uint32_t& r0, uint32_t& r1,
                                        uint32_t& r2, uint32_t& r3, uint32_t a) {
    asm volatile("ldmatrix.sync.aligned.m8n8.x4.shared.b16 {%0,%1,%2,%3}, [%4];"
                 : "=r"(r0), "=r"(r1), "=r"(r2), "=r"(r3) : "r"(a));
}
__device__ __forceinline__ void mma16816(float& d0, float& d1, float& d2, float& d3,
                                         uint32_t a0, uint32_t a1, uint32_t a2, uint32_t a3,
                                         uint32_t b0, uint32_t b1) {
    asm volatile("mma.sync.aligned.m16n8k16.row.col.f32.f16.f16.f32 "
                 "{%0,%1,%2,%3}, {%4,%5,%6,%7}, {%8,%9}, {%0,%1,%2,%3};"
                 : "+f"(d0), "+f"(d1), "+f"(d2), "+f"(d3)
                 : "r"(a0), "r"(a1), "r"(a2), "r"(a3), "r"(b0), "r"(b1));
}
__device__ __forceinline__ void cp16(uint32_t s, const void* g) {
    asm volatile("cp.async.cg.shared.global [%0], [%1], 16;" :: "r"(s), "l"(g));
}

template<int EPI>
__global__ __launch_bounds__(128, 2) void hgemm_k(
    const __half* __restrict__ Ah, const __half* __restrict__ Bh,
    const float* __restrict__ addend, float* __restrict__ C,
    __half* __restrict__ Hh,
    int M, int N, int K)
{
    extern __shared__ char smem[];
    uint32_t S0 = smem_u32(smem);

    int tid = threadIdx.x;
    int wid = tid >> 5, lane = tid & 31;
    int m0 = blockIdx.y << 7, n0 = blockIdx.x << 7;

    int seg = tid & 3, rr = tid >> 2;        // rr 0..31
    const __half* gA[2] = { Ah, Bh };
    int rbase[2] = { m0, n0 };

    int NK = K >> 5;

    // prefetch stages 0..2 (8 cp16 per thread per stage)
    #pragma unroll
    for (int st = 0; st < 3; st++) {
        uint32_t sb = S0 + st * STAGE_B;
        int k0 = st << 5;
        #pragma unroll
        for (int ten = 0; ten < 2; ten++) {
            #pragma unroll
            for (int r4 = 0; r4 < 4; r4++) {
                int row = rr + r4 * 32;
                const __half* G = gA[ten] + (size_t)(rbase[ten] + row) * K + k0 + seg * 8;
                cp16(sb + ten * TILE_B + row * 80 + seg * 16, G);
            }
        }
        asm volatile("cp.async.commit_group;");
    }

    // warp tiling: 2 m-warps x 2 n-warps, warp tile 64x64
    int wm = wid >> 1, wn = wid & 1;
    int m_off = wm * 64, n_off = wn * 64;

    uint32_t a_lo = (uint32_t)((lane & 15) * 80 + (lane >> 4) * 16);
    uint32_t b_lo = (uint32_t)(((lane & 7) + ((lane >> 4) << 3)) * 80 + (((lane >> 3) & 1) << 4));

    float acc[4][8][4];
    #pragma unroll
    for (int i = 0; i < 4; i++)
        #pragma unroll
        for (int j = 0; j < 8; j++)
            #pragma unroll
            for (int r = 0; r < 4; r++) acc[i][j][r] = 0.f;

    for (int kt = 0; kt < NK; kt++) {
        if      (kt + 2 < NK) asm volatile("cp.async.wait_group 2;");
        else if (kt + 1 < NK) asm volatile("cp.async.wait_group 1;");
        else                  asm volatile("cp.async.wait_group 0;");
        __syncthreads();

        if (kt + 3 < NK) {
            int st = (kt + 3) & 3;
            uint32_t sb = S0 + st * STAGE_B;
            int k0 = (kt + 3) << 5;
            #pragma unroll
            for (int ten = 0; ten < 2; ten++) {
                #pragma unroll
                for (int r4 = 0; r4 < 4; r4++) {
                    int row = rr + r4 * 32;
                    const __half* G = gA[ten] + (size_t)(rbase[ten] + row) * K + k0 + seg * 8;
                    cp16(sb + ten * TILE_B + row * 80 + seg * 16, G);
                }
            }
            asm volatile("cp.async.commit_group;");
        }

        uint32_t base = S0 + (kt & 3) * STAGE_B;
        uint32_t tA = base, tB = base + TILE_B;

        #pragma unroll
        for (int kk = 0; kk < 2; kk++) {
            uint32_t koff = (uint32_t)(kk * 32);
            uint32_t ah[4][4];
            #pragma unroll
            for (int mi = 0; mi < 4; mi++) {
                uint32_t off = (uint32_t)((m_off + mi*16) * 80) + koff + a_lo;
                ldsm_x4(ah[mi][0], ah[mi][1], ah[mi][2], ah[mi][3], tA + off);
            }
            uint32_t bh[8][2];
            #pragma unroll
            for (int nj = 0; nj < 4; nj++) {
                uint32_t off = (uint32_t)((n_off + nj*16) * 80) + koff + b_lo;
                uint32_t r0, r1, r2, r3;
                ldsm_x4(r0, r1, r2, r3, tB + off);
                bh[nj*2][0] = r0; bh[nj*2][1] = r1; bh[nj*2+1][0] = r2; bh[nj*2+1][1] = r3;
            }
            #pragma unroll
            for (int mi = 0; mi < 4; mi++)
                #pragma unroll
                for (int ni = 0; ni < 8; ni++)
                    mma16816(acc[mi][ni][0], acc[mi][ni][1], acc[mi][ni][2], acc[mi][ni][3],
                             ah[mi][0], ah[mi][1], ah[mi][2], ah[mi][3], bh[ni][0], bh[ni][1]);
        }
        __syncthreads();
    }

    // epilogue
    int rbase_m = m0 + m_off + (lane >> 2);
    #pragma unroll
    for (int mi = 0; mi < 4; mi++) {
        #pragma unroll
        for (int ni = 0; ni < 8; ni++) {
            int row = rbase_m + mi * 16;
            if (EPI == 2) {
                // even col = gate, odd col = up (interleaved weight columns)
                int c = n_off + ni*8 + (lane & 3) * 2;
                int j = (n0 + c) >> 1;
                int hw = N >> 1;
                float h1v = silu_f(acc[mi][ni][0]) * acc[mi][ni][1];
                float h2v = silu_f(acc[mi][ni][2]) * acc[mi][ni][3];
                Hh[(size_t)row * hw + j]     = __float2half(h1v);
                Hh[(size_t)(row+8) * hw + j] = __float2half(h2v);
            } else {
                int col = n0 + n_off + ni*8 + (lane & 3) * 2;
                float2 v0 = { acc[mi][ni][0], acc[mi][ni][1] };
                float2 v1 = { acc[mi][ni][2], acc[mi][ni][3] };
                if (EPI == 1) {
                    float2 a0 = *(const float2*)(addend + (size_t)row * N + col);
                    float2 a1 = *(const float2*)(addend + (size_t)(row + 8) * N + col);
                    v0.x += a0.x; v0.y += a0.y; v1.x += a1.x; v1.y += a1.y;
                }
                *(float2*)(C + (size_t)row * N + col) = v0;
                *(float2*)(C + (size_t)(row + 8) * N + col) = v1;
            }
        }
    }
}

// ---------------- beta/alpha projection ---------------------------------------
__global__ __launch_bounds__(128) void bgproj_k(const float* __restrict__ xn,
                                                const float* __restrict__ wb,
                                                const float* __restrict__ wg,
                                                float* __restrict__ ba)
{
    int m = blockIdx.x;
    int tid = threadIdx.x;
    float accb[8], accg[8];
    #pragma unroll
    for (int j = 0; j < 8; j++) { accb[j] = 0.f; accg[j] = 0.f; }

    const float* xr = xn + (size_t)m * D_ + tid*8;
    #pragma unroll
    for (int u = 0; u < 8; u++) {
        float xv = xr[u];
        int krow = tid*8 + u;
        const float4* wbp = (const float4*)(wb + (size_t)krow * H_);
        const float4* wgp = (const float4*)(wg + (size_t)krow * H_);
        float4 b0 = wbp[0], b1 = wbp[1];
        float4 g0 = wgp[0], g1 = wgp[1];
        accb[0] += xv*b0.x; accb[1] += xv*b0.y; accb[2] += xv*b0.z; accb[3] += xv*b0.w;
        accb[4] += xv*b1.x; accb[5] += xv*b1.y; accb[6] += xv*b1.z; accb[7] += xv*b1.w;
        accg[0] += xv*g0.x; accg[1] += xv*g0.y; accg[2] += xv*g0.z; accg[3] += xv*g0.w;
        accg[4] += xv*g1.x; accg[5] += xv*g1.y; accg[6] += xv*g1.z; accg[7] += xv*g1.w;
    }
    __shared__ float red[16][128];
    #pragma unroll
    for (int j = 0; j < 8; j++) { red[j][tid] = accb[j]; red[8+j][tid] = accg[j]; }
    __syncthreads();
    if (tid < 16) {
        float s = 0.f;
        for (int i = 0; i < 128; i++) s += red[tid][i];
        float val = sigmoid_f(s);
        int h = tid & 7;
        int which = tid >> 3;
        ba[((size_t)m * H_ + h)*2 + which] = val;
    }
}

// ---------------- gated DeltaNet recurrence -----------------------------------
// Reads fused qkv (stride 3072); writes o directly as fp16.
__global__ __launch_bounds__(128) void deltarec_k(const float* __restrict__ qkv,
                                                  const float* __restrict__ ba,
                                                  const float* __restrict__ s0,
                                                  __half* __restrict__ oh,
                                                  float* __restrict__ sout)
{
    int b = blockIdx.z, h = blockIdx.y, chunk = blockIdx.x;
    int tid = threadIdx.x;
    int warp = tid >> 5, lane = tid & 31;
    int grp = lane >> 4;
    int idx = lane & 15;
    int col = chunk*8 + warp*2 + grp;
    int r0  = idx * 8;

    float s[8];
    {
        const float* sp = s0 + (((size_t)(b*H_ + h)*DH_) + r0)*DH_ + col;
        #pragma unroll
        for (int i = 0; i < 8; i++) s[i] = sp[(size_t)i * DH_];
    }

    const float* base = qkv + (size_t)b * T_ * QKV_N + h * DH_;
    const float* qp  = base + r0;
    const float* kp  = base + 1024 + r0;
    const float* vp  = base + 2048 + col;
    const float* bap = ba + ((size_t)b * T_) * (H_*2) + h*2;
    size_t ooff = (size_t)b * T_ * D_ + (size_t)h * DH_ + col;

    float4 k0 = *(const float4*)(kp);
    float4 k1 = *(const float4*)(kp + 4);
    float4 q0 = *(const float4*)(qp);
    float4 q1 = *(const float4*)(qp + 4);
    float vv = *vp;
    float bb = bap[0];
    float aa = bap[1];

    for (int t = 0; t < T_; t++) {
        int tn = (t + 1 < T_) ? t + 1 : t;
        float4 nk0 = *(const float4*)(kp + (size_t)tn*QKV_N);
        float4 nk1 = *(const float4*)(kp + (size_t)tn*QKV_N + 4);
        float4 nq0 = *(const float4*)(qp + (size_t)tn*QKV_N);
        float4 nq1 = *(const float4*)(qp + (size_t)tn*QKV_N + 4);
        float nvv  = vp [(size_t)tn*QKV_N];
        float nbb  = bap[(size_t)tn*16];
        float naa  = bap[(size_t)tn*16 + 1];

        float kr[8] = {k0.x,k0.y,k0.z,k0.w,k1.x,k1.y,k1.z,k1.w};
        float qr[8] = {q0.x,q0.y,q0.z,q0.w,q1.x,q1.y,q1.z,q1.w};

        float pred = 0.f, po = 0.f, qk = 0.f;
        #pragma unroll
        for (int i = 0; i < 8; i++) {
            float sv = s[i] * aa;
            s[i] = sv;
            pred += kr[i] * sv;
            po   += qr[i] * sv;
            qk   += kr[i] * qr[i];
        }
        #pragma unroll
        for (int m = 1; m < 16; m <<= 1) {
            pred += __shfl_xor_sync(0xffffffffu, pred, m);
            po   += __shfl_xor_sync(0xffffffffu, po,   m);
            qk   += __shfl_xor_sync(0xffffffffu, qk,   m);
        }
        float dv = bb * (vv - pred);
        float ov = po + qk * dv;
        #pragma unroll
        for (int i = 0; i < 8; i++) s[i] += kr[i] * dv;

        if (idx == 0) oh[ooff + (size_t)t*D_] = __float2half(ov);

        k0 = nk0; k1 = nk1; q0 = nq0; q1 = nq1;
        vv = nvv; bb = nbb; aa = naa;
    }

    float* sp = sout + (((size_t)(b*H_ + h)*DH_) + r0)*DH_ + col;
    #pragma unroll
    for (int i = 0; i < 8; i++) sp[(size_t)i * DH_] = s[i];
}

// ---------------- launcher -----------------------------------------------------
struct Ptrs {
    float *xn, *qkv, *ba;
    __half *xh, *oh, *hh;
    __half *wqkv, *wo, *wgu, *wd;
    bool init = false;
};
static Ptrs P;

extern "C" void kernel_launch(void* const* d_in, const int* in_sizes, int n_in,
                              void* d_out, int out_size)
{
    const float* x   = (const float*)d_in[0];
    const float* st0 = (const float*)d_in[1];
    const float* wq  = (const float*)d_in[2];
    const float* wk  = (const float*)d_in[3];
    const float* wv  = (const float*)d_in[4];
    const float* wb  = (const float*)d_in[5];
    const float* wg  = (const float*)d_in[6];
    const float* wo  = (const float*)d_in[7];
    const float* wgate = (const float*)d_in[8];
    const float* wup   = (const float*)d_in[9];
    const float* wdown = (const float*)d_in[10];

    float* out = (float*)d_out;   // [x (4194304) | new_state (262144)]
    float* y   = out;
    float* stO = out + X_ELEMS;

    if (!P.init) {
        cudaGetSymbolAddress((void**)&P.xn,  g_xn);
        cudaGetSymbolAddress((void**)&P.qkv, g_qkv);
        cudaGetSymbolAddress((void**)&P.ba,  g_ba);
        cudaGetSymbolAddress((void**)&P.xh,  g_xh);
        cudaGetSymbolAddress((void**)&P.oh,  g_oh);
        cudaGetSymbolAddress((void**)&P.hh,  g_hh);
        cudaGetSymbolAddress((void**)&P.wqkv, g_wqkv);
        cudaGetSymbolAddress((void**)&P.wo,   g_wo);
        cudaGetSymbolAddress((void**)&P.wgu,  g_wgu);
        cudaGetSymbolAddress((void**)&P.wd,   g_wd);
        cudaFuncSetAttribute(hgemm_k<0>, cudaFuncAttributeMaxDynamicSharedMemorySize, HG_SMEM);
        cudaFuncSetAttribute(hgemm_k<1>, cudaFuncAttributeMaxDynamicSharedMemorySize, HG_SMEM);
        cudaFuncSetAttribute(hgemm_k<2>, cudaFuncAttributeMaxDynamicSharedMemorySize, HG_SMEM);
        P.init = true;
    }

    // weight transposes -> fp16 [N][K]
    tsplit_k<<<dim3(D_/32, D_/32), 256>>>(wq, P.wqkv, D_, D_, 1, 0);
    tsplit_k<<<dim3(D_/32, D_/32), 256>>>(wk, P.wqkv, D_, D_, 1, 1024);
    tsplit_k<<<dim3(D_/32, D_/32), 256>>>(wv, P.wqkv, D_, D_, 1, 2048);
    tsplit_k<<<dim3(D_/32, D_/32), 256>>>(wo, P.wo,   D_, D_, 1, 0);
    tsplit_k<<<dim3(F_/32, D_/32), 256>>>(wgate, P.wgu, D_, F_, 2, 0);
    tsplit_k<<<dim3(F_/32, D_/32), 256>>>(wup,   P.wgu, D_, F_, 2, 1);
    tsplit_k<<<dim3(D_/32, F_/32), 256>>>(wdown, P.wd,  F_, D_, 1, 0);

    // 1) xn = rmsnorm(x) -> fp16 + fp32 (for bgproj)
    rmsnorm_h_k<<<M_, 256>>>(x, P.xh, P.xn);

    // 2) fused qkv projection + gates
    hgemm_k<0><<<dim3(QKV_N/128, M_/128), 128, HG_SMEM>>>(
        P.xh, P.wqkv, nullptr, P.qkv, nullptr, M_, QKV_N, D_);
    bgproj_k<<<M_, 128>>>(P.xn, wb, wg, P.ba);

    // 3) silu + per-head L2 norm (q,k); silu (v) — fused over qkv
    silul2_qkv_k<<<(M_*24)/8, 256>>>(P.qkv);

    // 4) recurrence -> o (fp16), final state
    deltarec_k<<<dim3(16, H_, B_), 128>>>(P.qkv, P.ba, st0, P.oh, stO);

    // 5) y = x + o @ wo
    hgemm_k<1><<<dim3(D_/128, M_/128), 128, HG_SMEM>>>(
        P.oh, P.wo, x, y, nullptr, M_, D_, D_);

    // 6) yn = rmsnorm(y) -> fp16; fused gate/up GEMM with swiglu epilogue
    rmsnorm_h_k<<<M_, 256>>>(y, P.xh, nullptr);
    hgemm_k<2><<<dim3(2*F_/128, M_/128), 128, HG_SMEM>>>(
        P.xh, P.wgu, nullptr, nullptr, P.hh, M_, 2*F_, D_);

    // 7) out = y + h @ w_down
    hgemm_k<1><<<dim3(D_/128, M_/128), 128, HG_SMEM>>>(
        P.hh, P.wd, y, y, nullptr, M_, D_, F_);
}

// round 9
// speedup vs baseline: 1.7363x; 1.0086x over previous
#include <cuda_runtime.h>
#include <cuda_fp16.h>
#include <cstdint>

#define B_  2
#define T_  2048
#define D_  1024
#define F_  4096
#define H_  8
#define DH_ 128
#define M_  (B_*T_)              // 4096 rows
#define X_ELEMS (M_*D_)          // 4194304
#define QKV_N 3072

// ---------------- scratch (static device memory; no allocation at runtime) ----
static __device__ float g_xn [M_*D_];        // fp32 rmsnorm(x) (bgproj)
static __device__ float g_qkv[M_*QKV_N];     // fused q|k|v fp32
static __device__ float g_ba [M_*H_*2];

static __device__ __half g_xh[M_*D_];        // A operand fp16 (xn / yn)
static __device__ __half g_oh[M_*D_];        // deltanet out fp16
static __device__ __half g_hh[M_*F_];        // swiglu out fp16

static __device__ __half g_wqkv[QKV_N*D_];
static __device__ __half g_wo  [D_*D_];
static __device__ __half g_wgu [2*F_*D_];    // interleaved (gate,up) columns
static __device__ __half g_wd  [D_*F_];

__device__ __forceinline__ float silu_f(float x){ return x / (1.0f + expf(-x)); }
__device__ __forceinline__ float sigmoid_f(float x){ return 1.0f / (1.0f + expf(-x)); }

__device__ __forceinline__ uint32_t smem_u32(const void* p) {
    uint32_t a;
    asm("{ .reg .u64 t; cvta.to.shared.u64 t, %1; cvt.u32.u64 %0, t; }" : "=r"(a) : "l"(p));
    return a;
}

// ============================ elementwise / prep kernels ======================
// rmsnorm row of 1024 -> fp16 (+ optional fp32)
__global__ __launch_bounds__(256) void rmsnorm_h_k(const float* __restrict__ in,
                                                   __half* __restrict__ oh,
                                                   float* __restrict__ of)
{
    int row = blockIdx.x;
    int tid = threadIdx.x;
    const float4* ip = (const float4*)(in + (size_t)row * D_);
    float4 v = ip[tid];
    float ss = v.x*v.x + v.y*v.y + v.z*v.z + v.w*v.w;
    #pragma unroll
    for (int m = 16; m > 0; m >>= 1) ss += __shfl_xor_sync(0xffffffffu, ss, m);
    __shared__ float sred[8];
    if ((tid & 31) == 0) sred[tid >> 5] = ss;
    __syncthreads();
    float tot = 0.f;
    #pragma unroll
    for (int i = 0; i < 8; i++) tot += sred[i];
    float sc = rsqrtf(tot * (1.0f / D_) + 1e-6f);
    float4 o; o.x = v.x*sc; o.y = v.y*sc; o.z = v.z*sc; o.w = v.w*sc;
    __half2 h0 = __floats2half2_rn(o.x, o.y);
    __half2 h1 = __floats2half2_rn(o.z, o.w);
    size_t base2 = ((size_t)row * D_) / 2 + tid*2;
    ((__half2*)oh)[base2]   = h0;
    ((__half2*)oh)[base2+1] = h1;
    if (of) ((float4*)(of + (size_t)row * D_))[tid] = o;
}

// transpose [R][Cc] fp32 -> out[(c*cmul+cadd)][R] fp16
__global__ __launch_bounds__(256) void tsplit_k(const float* __restrict__ in,
                                                __half* __restrict__ oh,
                                                int R, int Cc, int cmul, int cadd)
{
    __shared__ float t[32][33];
    int tx = threadIdx.x & 31, ty = threadIdx.x >> 5;   // 32x8
    int c0 = blockIdx.x * 32, r0 = blockIdx.y * 32;
    #pragma unroll
    for (int i = 0; i < 4; i++)
        t[ty + i*8][tx] = in[(size_t)(r0 + ty + i*8) * Cc + c0 + tx];
    __syncthreads();
    #pragma unroll
    for (int i = 0; i < 4; i++) {
        int oc = ty + i*8;
        size_t oi = ((size_t)(c0 + oc) * cmul + cadd) * R + r0 + tx;
        oh[oi] = __float2half(t[tx][oc]);
    }
}

// silu (+L2 norm for q,k heads) over fused qkv rows of 128
__global__ __launch_bounds__(256) void silul2_qkv_k(float* __restrict__ qkv)
{
    int r = blockIdx.x * 8 + (threadIdx.x >> 5);   // row-of-128 index, 0..M*24-1
    int lane = threadIdx.x & 31;
    int m = r / 24, sec = r % 24;
    float4* p = (float4*)(qkv + (size_t)m * QKV_N + sec * 128) + lane;
    float4 x = *p;
    float4 s;
    s.x = silu_f(x.x); s.y = silu_f(x.y); s.z = silu_f(x.z); s.w = silu_f(x.w);
    if (sec < 16) {   // q and k heads get L2 norm
        float ss = s.x*s.x + s.y*s.y + s.z*s.z + s.w*s.w;
        #pragma unroll
        for (int m2 = 16; m2 > 0; m2 >>= 1) ss += __shfl_xor_sync(0xffffffffu, ss, m2);
        float sc = rsqrtf(ss + 1e-6f);
        s.x *= sc; s.y *= sc; s.z *= sc; s.w *= sc;
    }
    *p = s;
}

// ============================ mma.sync fp16 GEMM ==============================
// C[M,N] = (addend?) + A[M,K] @ Bt[N,K]^T, fp16 in, fp32 accumulate.
// Tile 128x128, BK=32, 128 threads (4 warps, warp tile 64x64), 4-stage cp.async,
// 2 CTAs/SM, ONE barrier per kt, all fragments batch-loaded before MMAs.
// EPI: 0 = write C fp32; 1 = C = addend + acc; 2 = swiglu -> fp16.
#define TILE_B (128*80)               // 10240 B per operand tile
#define STAGE_B (TILE_B*2)            // 20480 B per stage (A,B)
#define HG_SMEM (STAGE_B*4)           // 81920 B

__device__ __forceinline__ void ldsm_x4(uint32_t& r0, uint32_t& r1,
                                        uint32_t& r2, uint32_t& r3, uint32_t a) {
    asm volatile("ldmatrix.sync.aligned.m8n8.x4.shared.b16 {%0,%1,%2,%3}, [%4];"
                 : "=r"(r0), "=r"(r1), "=r"(r2), "=r"(r3) : "r"(a));
}
__device__ __forceinline__ void mma16816(float& d0, float& d1, float& d2, float& d3,
                                         uint32_t a0, uint32_t a1, uint32_t a2, uint32_t a3,
                                         uint32_t b0, uint32_t b1) {
    asm volatile("mma.sync.aligned.m16n8k16.row.col.f32.f16.f16.f32 "
                 "{%0,%1,%2,%3}, {%4,%5,%6,%7}, {%8,%9}, {%0,%1,%2,%3};"
                 : "+f"(d0), "+f"(d1), "+f"(d2), "+f"(d3)
                 : "r"(a0), "r"(a1), "r"(a2), "r"(a3), "r"(b0), "r"(b1));
}
__device__ __forceinline__ void cp16(uint32_t s, const void* g) {
    asm volatile("cp.async.cg.shared.global [%0], [%1], 16;" :: "r"(s), "l"(g));
}

template<int EPI>
__global__ __launch_bounds__(128, 2) void hgemm_k(
    const __half* __restrict__ Ah, const __half* __restrict__ Bh,
    const float* __restrict__ addend, float* __restrict__ C,
    __half* __restrict__ Hh,
    int M, int N, int K)
{
    extern __shared__ char smem[];
    uint32_t S0 = smem_u32(smem);

    int tid = threadIdx.x;
    int wid = tid >> 5, lane = tid & 31;
    int m0 = blockIdx.y << 7, n0 = blockIdx.x << 7;

    int seg = tid & 3, rr = tid >> 2;        // rr 0..31
    const __half* gA[2] = { Ah, Bh };
    int rbase[2] = { m0, n0 };

    int NK = K >> 5;

    // prefetch stages 0..2 (8 cp16 per thread per stage)
    #pragma unroll
    for (int st = 0; st < 3; st++) {
        uint32_t sb = S0 + st * STAGE_B;
        int k0 = st << 5;
        #pragma unroll
        for (int ten = 0; ten < 2; ten++) {
            #pragma unroll
            for (int r4 = 0; r4 < 4; r4++) {
                int row = rr + r4 * 32;
                const __half* G = gA[ten] + (size_t)(rbase[ten] + row) * K + k0 + seg * 8;
                cp16(sb + ten * TILE_B + row * 80 + seg * 16, G);
            }
        }
        asm volatile("cp.async.commit_group;");
    }

    // warp tiling: 2 m-warps x 2 n-warps, warp tile 64x64
    int wm = wid >> 1, wn = wid & 1;
    int m_off = wm * 64, n_off = wn * 64;

    uint32_t a_lo = (uint32_t)((lane & 15) * 80 + (lane >> 4) * 16);
    uint32_t b_lo = (uint32_t)(((lane & 7) + ((lane >> 4) << 3)) * 80 + (((lane >> 3) & 1) << 4));

    float acc[4][8][4];
    #pragma unroll
    for (int i = 0; i < 4; i++)
        #pragma unroll
        for (int j = 0; j < 8; j++)
            #pragma unroll
            for (int r = 0; r < 4; r++) acc[i][j][r] = 0.f;

    for (int kt = 0; kt < NK; kt++) {
        if      (kt + 2 < NK) asm volatile("cp.async.wait_group 2;");
        else if (kt + 1 < NK) asm volatile("cp.async.wait_group 1;");
        else                  asm volatile("cp.async.wait_group 0;");
        __syncthreads();
        // NOTE: single barrier per kt. Safe: prefetch at kt writes stage
        // (kt+3)&3 == (kt-1)&3, whose reads all warps completed before
        // arriving at THIS barrier (program order).

        if (kt + 3 < NK) {
            int st = (kt + 3) & 3;
            uint32_t sb = S0 + st * STAGE_B;
            int k0 = (kt + 3) << 5;
            #pragma unroll
            for (int ten = 0; ten < 2; ten++) {
                #pragma unroll
                for (int r4 = 0; r4 < 4; r4++) {
                    int row = rr + r4 * 32;
                    const __half* G = gA[ten] + (size_t)(rbase[ten] + row) * K + k0 + seg * 8;
                    cp16(sb + ten * TILE_B + row * 80 + seg * 16, G);
                }
            }
            asm volatile("cp.async.commit_group;");
        }

        uint32_t base = S0 + (kt & 3) * STAGE_B;
        uint32_t tA = base, tB = base + TILE_B;

        // batch-load ALL fragments for both kk halves, then run all MMAs
        uint32_t ah[2][4][4];
        uint32_t bh[2][8][2];
        #pragma unroll
        for (int kk = 0; kk < 2; kk++) {
            uint32_t koff = (uint32_t)(kk * 32);
            #pragma unroll
            for (int mi = 0; mi < 4; mi++) {
                uint32_t off = (uint32_t)((m_off + mi*16) * 80) + koff + a_lo;
                ldsm_x4(ah[kk][mi][0], ah[kk][mi][1], ah[kk][mi][2], ah[kk][mi][3], tA + off);
            }
            #pragma unroll
            for (int nj = 0; nj < 4; nj++) {
                uint32_t off = (uint32_t)((n_off + nj*16) * 80) + koff + b_lo;
                uint32_t r0, r1, r2, r3;
                ldsm_x4(r0, r1, r2, r3, tB + off);
                bh[kk][nj*2][0] = r0; bh[kk][nj*2][1] = r1;
                bh[kk][nj*2+1][0] = r2; bh[kk][nj*2+1][1] = r3;
            }
        }
        #pragma unroll
        for (int kk = 0; kk < 2; kk++)
            #pragma unroll
            for (int mi = 0; mi < 4; mi++)
                #pragma unroll
                for (int ni = 0; ni < 8; ni++)
                    mma16816(acc[mi][ni][0], acc[mi][ni][1], acc[mi][ni][2], acc[mi][ni][3],
                             ah[kk][mi][0], ah[kk][mi][1], ah[kk][mi][2], ah[kk][mi][3],
                             bh[kk][ni][0], bh[kk][ni][1]);
    }

    // epilogue
    int rbase_m = m0 + m_off + (lane >> 2);
    #pragma unroll
    for (int mi = 0; mi < 4; mi++) {
        #pragma unroll
        for (int ni = 0; ni < 8; ni++) {
            int row = rbase_m + mi * 16;
            if (EPI == 2) {
                // even col = gate, odd col = up (interleaved weight columns)
                int c = n_off + ni*8 + (lane & 3) * 2;
                int j = (n0 + c) >> 1;
                int hw = N >> 1;
                float h1v = silu_f(acc[mi][ni][0]) * acc[mi][ni][1];
                float h2v = silu_f(acc[mi][ni][2]) * acc[mi][ni][3];
                Hh[(size_t)row * hw + j]     = __float2half(h1v);
                Hh[(size_t)(row+8) * hw + j] = __float2half(h2v);
            } else {
                int col = n0 + n_off + ni*8 + (lane & 3) * 2;
                float2 v0 = { acc[mi][ni][0], acc[mi][ni][1] };
                float2 v1 = { acc[mi][ni][2], acc[mi][ni][3] };
                if (EPI == 1) {
                    float2 a0 = *(const float2*)(addend + (size_t)row * N + col);
                    float2 a1 = *(const float2*)(addend + (size_t)(row + 8) * N + col);
                    v0.x += a0.x; v0.y += a0.y; v1.x += a1.x; v1.y += a1.y;
                }
                *(float2*)(C + (size_t)row * N + col) = v0;
                *(float2*)(C + (size_t)(row + 8) * N + col) = v1;
            }
        }
    }
}

// ---------------- beta/alpha projection ---------------------------------------
__global__ __launch_bounds__(128) void bgproj_k(const float* __restrict__ xn,
                                                const float* __restrict__ wb,
                                                const float* __restrict__ wg,
                                                float* __restrict__ ba)
{
    int m = blockIdx.x;
    int tid = threadIdx.x;
    float accb[8], accg[8];
    #pragma unroll
    for (int j = 0; j < 8; j++) { accb[j] = 0.f; accg[j] = 0.f; }

    const float* xr = xn + (size_t)m * D_ + tid*8;
    #pragma unroll
    for (int u = 0; u < 8; u++) {
        float xv = xr[u];
        int krow = tid*8 + u;
        const float4* wbp = (const float4*)(wb + (size_t)krow * H_);
        const float4* wgp = (const float4*)(wg + (size_t)krow * H_);
        float4 b0 = wbp[0], b1 = wbp[1];
        float4 g0 = wgp[0], g1 = wgp[1];
        accb[0] += xv*b0.x; accb[1] += xv*b0.y; accb[2] += xv*b0.z; accb[3] += xv*b0.w;
        accb[4] += xv*b1.x; accb[5] += xv*b1.y; accb[6] += xv*b1.z; accb[7] += xv*b1.w;
        accg[0] += xv*g0.x; accg[1] += xv*g0.y; accg[2] += xv*g0.z; accg[3] += xv*g0.w;
        accg[4] += xv*g1.x; accg[5] += xv*g1.y; accg[6] += xv*g1.z; accg[7] += xv*g1.w;
    }
    __shared__ float red[16][128];
    #pragma unroll
    for (int j = 0; j < 8; j++) { red[j][tid] = accb[j]; red[8+j][tid] = accg[j]; }
    __syncthreads();
    if (tid < 16) {
        float s = 0.f;
        for (int i = 0; i < 128; i++) s += red[tid][i];
        float val = sigmoid_f(s);
        int h = tid & 7;
        int which = tid >> 3;
        ba[((size_t)m * H_ + h)*2 + which] = val;
    }
}

// ---------------- gated DeltaNet recurrence -----------------------------------
// Reads fused qkv (stride 3072); writes o directly as fp16.
__global__ __launch_bounds__(128) void deltarec_k(const float* __restrict__ qkv,
                                                  const float* __restrict__ ba,
                                                  const float* __restrict__ s0,
                                                  __half* __restrict__ oh,
                                                  float* __restrict__ sout)
{
    int b = blockIdx.z, h = blockIdx.y, chunk = blockIdx.x;
    int tid = threadIdx.x;
    int warp = tid >> 5, lane = tid & 31;
    int grp = lane >> 4;
    int idx = lane & 15;
    int col = chunk*8 + warp*2 + grp;
    int r0  = idx * 8;

    float s[8];
    {
        const float* sp = s0 + (((size_t)(b*H_ + h)*DH_) + r0)*DH_ + col;
        #pragma unroll
        for (int i = 0; i < 8; i++) s[i] = sp[(size_t)i * DH_];
    }

    const float* base = qkv + (size_t)b * T_ * QKV_N + h * DH_;
    const float* qp  = base + r0;
    const float* kp  = base + 1024 + r0;
    const float* vp  = base + 2048 + col;
    const float* bap = ba + ((size_t)b * T_) * (H_*2) + h*2;
    size_t ooff = (size_t)b * T_ * D_ + (size_t)h * DH_ + col;

    float4 k0 = *(const float4*)(kp);
    float4 k1 = *(const float4*)(kp + 4);
    float4 q0 = *(const float4*)(qp);
    float4 q1 = *(const float4*)(qp + 4);
    float vv = *vp;
    float bb = bap[0];
    float aa = bap[1];

    for (int t = 0; t < T_; t++) {
        int tn = (t + 1 < T_) ? t + 1 : t;
        float4 nk0 = *(const float4*)(kp + (size_t)tn*QKV_N);
        float4 nk1 = *(const float4*)(kp + (size_t)tn*QKV_N + 4);
        float4 nq0 = *(const float4*)(qp + (size_t)tn*QKV_N);
        float4 nq1 = *(const float4*)(qp + (size_t)tn*QKV_N + 4);
        float nvv  = vp [(size_t)tn*QKV_N];
        float nbb  = bap[(size_t)tn*16];
        float naa  = bap[(size_t)tn*16 + 1];

        float kr[8] = {k0.x,k0.y,k0.z,k0.w,k1.x,k1.y,k1.z,k1.w};
        float qr[8] = {q0.x,q0.y,q0.z,q0.w,q1.x,q1.y,q1.z,q1.w};

        float pred = 0.f, po = 0.f, qk = 0.f;
        #pragma unroll
        for (int i = 0; i < 8; i++) {
            float sv = s[i] * aa;
            s[i] = sv;
            pred += kr[i] * sv;
            po   += qr[i] * sv;
            qk   += kr[i] * qr[i];
        }
        #pragma unroll
        for (int m = 1; m < 16; m <<= 1) {
            pred += __shfl_xor_sync(0xffffffffu, pred, m);
            po   += __shfl_xor_sync(0xffffffffu, po,   m);
            qk   += __shfl_xor_sync(0xffffffffu, qk,   m);
        }
        float dv = bb * (vv - pred);
        float ov = po + qk * dv;
        #pragma unroll
        for (int i = 0; i < 8; i++) s[i] += kr[i] * dv;

        if (idx == 0) oh[ooff + (size_t)t*D_] = __float2half(ov);

        k0 = nk0; k1 = nk1; q0 = nq0; q1 = nq1;
        vv = nvv; bb = nbb; aa = naa;
    }

    float* sp = sout + (((size_t)(b*H_ + h)*DH_) + r0)*DH_ + col;
    #pragma unroll
    for (int i = 0; i < 8; i++) sp[(size_t)i * DH_] = s[i];
}

// ---------------- launcher -----------------------------------------------------
struct Ptrs {
    float *xn, *qkv, *ba;
    __half *xh, *oh, *hh;
    __half *wqkv, *wo, *wgu, *wd;
    bool init = false;
};
static Ptrs P;

extern "C" void kernel_launch(void* const* d_in, const int* in_sizes, int n_in,
                              void* d_out, int out_size)
{
    const float* x   = (const float*)d_in[0];
    const float* st0 = (const float*)d_in[1];
    const float* wq  = (const float*)d_in[2];
    const float* wk  = (const float*)d_in[3];
    const float* wv  = (const float*)d_in[4];
    const float* wb  = (const float*)d_in[5];
    const float* wg  = (const float*)d_in[6];
    const float* wo  = (const float*)d_in[7];
    const float* wgate = (const float*)d_in[8];
    const float* wup   = (const float*)d_in[9];
    const float* wdown = (const float*)d_in[10];

    float* out = (float*)d_out;   // [x (4194304) | new_state (262144)]
    float* y   = out;
    float* stO = out + X_ELEMS;

    if (!P.init) {
        cudaGetSymbolAddress((void**)&P.xn,  g_xn);
        cudaGetSymbolAddress((void**)&P.qkv, g_qkv);
        cudaGetSymbolAddress((void**)&P.ba,  g_ba);
        cudaGetSymbolAddress((void**)&P.xh,  g_xh);
        cudaGetSymbolAddress((void**)&P.oh,  g_oh);
        cudaGetSymbolAddress((void**)&P.hh,  g_hh);
        cudaGetSymbolAddress((void**)&P.wqkv, g_wqkv);
        cudaGetSymbolAddress((void**)&P.wo,   g_wo);
        cudaGetSymbolAddress((void**)&P.wgu,  g_wgu);
        cudaGetSymbolAddress((void**)&P.wd,   g_wd);
        cudaFuncSetAttribute(hgemm_k<0>, cudaFuncAttributeMaxDynamicSharedMemorySize, HG_SMEM);
        cudaFuncSetAttribute(hgemm_k<1>, cudaFuncAttributeMaxDynamicSharedMemorySize, HG_SMEM);
        cudaFuncSetAttribute(hgemm_k<2>, cudaFuncAttributeMaxDynamicSharedMemorySize, HG_SMEM);
        P.init = true;
    }

    // weight transposes -> fp16 [N][K]
    tsplit_k<<<dim3(D_/32, D_/32), 256>>>(wq, P.wqkv, D_, D_, 1, 0);
    tsplit_k<<<dim3(D_/32, D_/32), 256>>>(wk, P.wqkv, D_, D_, 1, 1024);
    tsplit_k<<<dim3(D_/32, D_/32), 256>>>(wv, P.wqkv, D_, D_, 1, 2048);
    tsplit_k<<<dim3(D_/32, D_/32), 256>>>(wo, P.wo,   D_, D_, 1, 0);
    tsplit_k<<<dim3(F_/32, D_/32), 256>>>(wgate, P.wgu, D_, F_, 2, 0);
    tsplit_k<<<dim3(F_/32, D_/32), 256>>>(wup,   P.wgu, D_, F_, 2, 1);
    tsplit_k<<<dim3(D_/32, F_/32), 256>>>(wdown, P.wd,  F_, D_, 1, 0);

    // 1) xn = rmsnorm(x) -> fp16 + fp32 (for bgproj)
    rmsnorm_h_k<<<M_, 256>>>(x, P.xh, P.xn);

    // 2) fused qkv projection + gates
    hgemm_k<0><<<dim3(QKV_N/128, M_/128), 128, HG_SMEM>>>(
        P.xh, P.wqkv, nullptr, P.qkv, nullptr, M_, QKV_N, D_);
    bgproj_k<<<M_, 128>>>(P.xn, wb, wg, P.ba);

    // 3) silu + per-head L2 norm (q,k); silu (v) — fused over qkv
    silul2_qkv_k<<<(M_*24)/8, 256>>>(P.qkv);

    // 4) recurrence -> o (fp16), final state
    deltarec_k<<<dim3(16, H_, B_), 128>>>(P.qkv, P.ba, st0, P.oh, stO);

    // 5) y = x + o @ wo
    hgemm_k<1><<<dim3(D_/128, M_/128), 128, HG_SMEM>>>(
        P.oh, P.wo, x, y, nullptr, M_, D_, D_);

    // 6) yn = rmsnorm(y) -> fp16; fused gate/up GEMM with swiglu epilogue
    rmsnorm_h_k<<<M_, 256>>>(y, P.xh, nullptr);
    hgemm_k<2><<<dim3(2*F_/128, M_/128), 128, HG_SMEM>>>(
        P.xh, P.wgu, nullptr, nullptr, P.hh, M_, 2*F_, D_);

    // 7) out = y + h @ w_down
    hgemm_k<1><<<dim3(D_/128, M_/128), 128, HG_SMEM>>>(
        P.hh, P.wd, y, y, nullptr, M_, D_, F_);
}

// round 11
// speedup vs baseline: 1.7376x; 1.0007x over previous
#include <cuda_runtime.h>
#include <cuda_fp16.h>
#include <cstdint>

#define B_  2
#define T_  2048
#define D_  1024
#define F_  4096
#define H_  8
#define DH_ 128
#define M_  (B_*T_)              // 4096 rows
#define X_ELEMS (M_*D_)          // 4194304
#define QKV_N 3072

// ---------------- scratch (static device memory; no allocation at runtime) ----
static __device__ float g_xn [M_*D_];        // fp32 rmsnorm(x) (bgproj)
static __device__ float g_qkv[M_*QKV_N];     // fused q|k|v fp32
static __device__ float g_ba [M_*H_*2];

static __device__ __half g_xh[M_*D_];        // A operand fp16 (xn / yn)
static __device__ __half g_oh[M_*D_];        // deltanet out fp16
static __device__ __half g_hh[M_*F_];        // swiglu out fp16

static __device__ __half g_wqkv[QKV_N*D_];
static __device__ __half g_wo  [D_*D_];
static __device__ __half g_wgu [2*F_*D_];    // interleaved (gate,up) columns
static __device__ __half g_wd  [D_*F_];

__device__ __forceinline__ float silu_f(float x){ return x / (1.0f + expf(-x)); }
__device__ __forceinline__ float sigmoid_f(float x){ return 1.0f / (1.0f + expf(-x)); }

__device__ __forceinline__ uint32_t smem_u32(const void* p) {
    uint32_t a;
    asm("{ .reg .u64 t; cvta.to.shared.u64 t, %1; cvt.u32.u64 %0, t; }" : "=r"(a) : "l"(p));
    return a;
}

// ============================ elementwise / prep kernels ======================
// rmsnorm row of 1024 -> fp16 (+ optional fp32)
__global__ __launch_bounds__(256) void rmsnorm_h_k(const float* __restrict__ in,
                                                   __half* __restrict__ oh,
                                                   float* __restrict__ of)
{
    int row = blockIdx.x;
    int tid = threadIdx.x;
    const float4* ip = (const float4*)(in + (size_t)row * D_);
    float4 v = ip[tid];
    float ss = v.x*v.x + v.y*v.y + v.z*v.z + v.w*v.w;
    #pragma unroll
    for (int m = 16; m > 0; m >>= 1) ss += __shfl_xor_sync(0xffffffffu, ss, m);
    __shared__ float sred[8];
    if ((tid & 31) == 0) sred[tid >> 5] = ss;
    __syncthreads();
    float tot = 0.f;
    #pragma unroll
    for (int i = 0; i < 8; i++) tot += sred[i];
    float sc = rsqrtf(tot * (1.0f / D_) + 1e-6f);
    float4 o; o.x = v.x*sc; o.y = v.y*sc; o.z = v.z*sc; o.w = v.w*sc;
    __half2 h0 = __floats2half2_rn(o.x, o.y);
    __half2 h1 = __floats2half2_rn(o.z, o.w);
    size_t base2 = ((size_t)row * D_) / 2 + tid*2;
    ((__half2*)oh)[base2]   = h0;
    ((__half2*)oh)[base2+1] = h1;
    if (of) ((float4*)(of + (size_t)row * D_))[tid] = o;
}

// transpose [R][Cc] fp32 -> out[(c*cmul+cadd)][R] fp16
__global__ __launch_bounds__(256) void tsplit_k(const float* __restrict__ in,
                                                __half* __restrict__ oh,
                                                int R, int Cc, int cmul, int cadd)
{
    __shared__ float t[32][33];
    int tx = threadIdx.x & 31, ty = threadIdx.x >> 5;   // 32x8
    int c0 = blockIdx.x * 32, r0 = blockIdx.y * 32;
    #pragma unroll
    for (int i = 0; i < 4; i++)
        t[ty + i*8][tx] = in[(size_t)(r0 + ty + i*8) * Cc + c0 + tx];
    __syncthreads();
    #pragma unroll
    for (int i = 0; i < 4; i++) {
        int oc = ty + i*8;
        size_t oi = ((size_t)(c0 + oc) * cmul + cadd) * R + r0 + tx;
        oh[oi] = __float2half(t[tx][oc]);
    }
}

// silu (+L2 norm for q,k heads) over fused qkv rows of 128
__global__ __launch_bounds__(256) void silul2_qkv_k(float* __restrict__ qkv)
{
    int r = blockIdx.x * 8 + (threadIdx.x >> 5);   // row-of-128 index, 0..M*24-1
    int lane = threadIdx.x & 31;
    int m = r / 24, sec = r % 24;
    float4* p = (float4*)(qkv + (size_t)m * QKV_N + sec * 128) + lane;
    float4 x = *p;
    float4 s;
    s.x = silu_f(x.x); s.y = silu_f(x.y); s.z = silu_f(x.z); s.w = silu_f(x.w);
    if (sec < 16) {   // q and k heads get L2 norm
        float ss = s.x*s.x + s.y*s.y + s.z*s.z + s.w*s.w;
        #pragma unroll
        for (int m2 = 16; m2 > 0; m2 >>= 1) ss += __shfl_xor_sync(0xffffffffu, ss, m2);
        float sc = rsqrtf(ss + 1e-6f);
        s.x *= sc; s.y *= sc; s.z *= sc; s.w *= sc;
    }
    *p = s;
}

// ============================ mma.sync fp16 GEMM ==============================
// C[M,N] = (addend?) + A[M,K] @ Bt[N,K]^T, fp16 in, fp32 accumulate.
// Tile 128x128, BK=32, 128 threads (4 warps, warp tile 64x64), 4-stage cp.async,
// 2 CTAs/SM, ONE barrier per kt, fragments batch-loaded.
// EPI: 0 = write C fp32; 1 = C = addend + acc; 2 = swiglu -> fp16.
#define TILE_B (128*80)               // 10240 B per operand tile
#define STAGE_B (TILE_B*2)            // 20480 B per stage (A,B)
#define HG_SMEM (STAGE_B*4)           // 81920 B

__device__ __forceinline__ void ldsm_x4(uint32_t& r0, uint32_t& r1,
                                        uint32_t& r2, uint32_t& r3, uint32_t a) {
    asm volatile("ldmatrix.sync.aligned.m8n8.x4.shared.b16 {%0,%1,%2,%3}, [%4];"
                 : "=r"(r0), "=r"(r1), "=r"(r2), "=r"(r3) : "r"(a));
}
__device__ __forceinline__ void mma16816(float& d0, float& d1, float& d2, float& d3,
                                         uint32_t a0, uint32_t a1, uint32_t a2, uint32_t a3,
                                         uint32_t b0, uint32_t b1) {
    asm volatile("mma.sync.aligned.m16n8k16.row.col.f32.f16.f16.f32 "
                 "{%0,%1,%2,%3}, {%4,%5,%6,%7}, {%8,%9}, {%0,%1,%2,%3};"
                 : "+f"(d0), "+f"(d1), "+f"(d2), "+f"(d3)
                 : "r"(a0), "r"(a1), "r"(a2), "r"(a3), "r"(b0), "r"(b1));
}
__device__ __forceinline__ void cp16(uint32_t s, const void* g) {
    asm volatile("cp.async.cg.shared.global [%0], [%1], 16;" :: "r"(s), "l"(g));
}

template<int EPI>
__global__ __launch_bounds__(128, 2) void hgemm_k(
    const __half* __restrict__ Ah, const __half* __restrict__ Bh,
    const float* __restrict__ addend, float* __restrict__ C,
    __half* __restrict__ Hh,
    int M, int N, int K)
{
    extern __shared__ char smem[];
    uint32_t S0 = smem_u32(smem);

    int tid = threadIdx.x;
    int wid = tid >> 5, lane = tid & 31;
    int m0 = blockIdx.y << 7, n0 = blockIdx.x << 7;

    int seg = tid & 3, rr = tid >> 2;        // rr 0..31
    const __half* gA[2] = { Ah, Bh };
    int rbase[2] = { m0, n0 };

    int NK = K >> 5;

    // prefetch stages 0..2 (8 cp16 per thread per stage)
    #pragma unroll
    for (int st = 0; st < 3; st++) {
        uint32_t sb = S0 + st * STAGE_B;
        int k0 = st << 5;
        #pragma unroll
        for (int ten = 0; ten < 2; ten++) {
            #pragma unroll
            for (int r4 = 0; r4 < 4; r4++) {
                int row = rr + r4 * 32;
                const __half* G = gA[ten] + (size_t)(rbase[ten] + row) * K + k0 + seg * 8;
                cp16(sb + ten * TILE_B + row * 80 + seg * 16, G);
            }
        }
        asm volatile("cp.async.commit_group;");
    }

    // warp tiling: 2 m-warps x 2 n-warps, warp tile 64x64
    int wm = wid >> 1, wn = wid & 1;
    int m_off = wm * 64, n_off = wn * 64;

    uint32_t a_lo = (uint32_t)((lane & 15) * 80 + (lane >> 4) * 16);
    uint32_t b_lo = (uint32_t)(((lane & 7) + ((lane >> 4) << 3)) * 80 + (((lane >> 3) & 1) << 4));

    float acc[4][8][4];
    #pragma unroll
    for (int i = 0; i < 4; i++)
        #pragma unroll
        for (int j = 0; j < 8; j++)
            #pragma unroll
            for (int r = 0; r < 4; r++) acc[i][j][r] = 0.f;

    for (int kt = 0; kt < NK; kt++) {
        if      (kt + 2 < NK) asm volatile("cp.async.wait_group 2;");
        else if (kt + 1 < NK) asm volatile("cp.async.wait_group 1;");
        else                  asm volatile("cp.async.wait_group 0;");
        __syncthreads();
        // single barrier per kt: prefetch below writes stage (kt+3)&3 ==
        // (kt-1)&3, whose reads finished before all warps reached this barrier.

        if (kt + 3 < NK) {
            int st = (kt + 3) & 3;
            uint32_t sb = S0 + st * STAGE_B;
            int k0 = (kt + 3) << 5;
            #pragma unroll
            for (int ten = 0; ten < 2; ten++) {
                #pragma unroll
                for (int r4 = 0; r4 < 4; r4++) {
                    int row = rr + r4 * 32;
                    const __half* G = gA[ten] + (size_t)(rbase[ten] + row) * K + k0 + seg * 8;
                    cp16(sb + ten * TILE_B + row * 80 + seg * 16, G);
                }
            }
            asm volatile("cp.async.commit_group;");
        }

        uint32_t base = S0 + (kt & 3) * STAGE_B;
        uint32_t tA = base, tB = base + TILE_B;

        // batch-load ALL fragments for both kk halves, then run all MMAs
        uint32_t ah[2][4][4];
        uint32_t bh[2][8][2];
        #pragma unroll
        for (int kk = 0; kk < 2; kk++) {
            uint32_t koff = (uint32_t)(kk * 32);
            #pragma unroll
            for (int mi = 0; mi < 4; mi++) {
                uint32_t off = (uint32_t)((m_off + mi*16) * 80) + koff + a_lo;
                ldsm_x4(ah[kk][mi][0], ah[kk][mi][1], ah[kk][mi][2], ah[kk][mi][3], tA + off);
            }
            #pragma unroll
            for (int nj = 0; nj < 4; nj++) {
                uint32_t off = (uint32_t)((n_off + nj*16) * 80) + koff + b_lo;
                uint32_t r0, r1, r2, r3;
                ldsm_x4(r0, r1, r2, r3, tB + off);
                bh[kk][nj*2][0] = r0; bh[kk][nj*2][1] = r1;
                bh[kk][nj*2+1][0] = r2; bh[kk][nj*2+1][1] = r3;
            }
        }
        #pragma unroll
        for (int kk = 0; kk < 2; kk++)
            #pragma unroll
            for (int mi = 0; mi < 4; mi++)
                #pragma unroll
                for (int ni = 0; ni < 8; ni++)
                    mma16816(acc[mi][ni][0], acc[mi][ni][1], acc[mi][ni][2], acc[mi][ni][3],
                             ah[kk][mi][0], ah[kk][mi][1], ah[kk][mi][2], ah[kk][mi][3],
                             bh[kk][ni][0], bh[kk][ni][1]);
    }

    // epilogue
    int rbase_m = m0 + m_off + (lane >> 2);
    #pragma unroll
    for (int mi = 0; mi < 4; mi++) {
        #pragma unroll
        for (int ni = 0; ni < 8; ni++) {
            int row = rbase_m + mi * 16;
            if (EPI == 2) {
                // even col = gate, odd col = up (interleaved weight columns)
                int c = n_off + ni*8 + (lane & 3) * 2;
                int j = (n0 + c) >> 1;
                int hw = N >> 1;
                float h1v = silu_f(acc[mi][ni][0]) * acc[mi][ni][1];
                float h2v = silu_f(acc[mi][ni][2]) * acc[mi][ni][3];
                Hh[(size_t)row * hw + j]     = __float2half(h1v);
                Hh[(size_t)(row+8) * hw + j] = __float2half(h2v);
            } else {
                int col = n0 + n_off + ni*8 + (lane & 3) * 2;
                float2 v0 = { acc[mi][ni][0], acc[mi][ni][1] };
                float2 v1 = { acc[mi][ni][2], acc[mi][ni][3] };
                if (EPI == 1) {
                    float2 a0 = *(const float2*)(addend + (size_t)row * N + col);
                    float2 a1 = *(const float2*)(addend + (size_t)(row + 8) * N + col);
                    v0.x += a0.x; v0.y += a0.y; v1.x += a1.x; v1.y += a1.y;
                }
                *(float2*)(C + (size_t)row * N + col) = v0;
                *(float2*)(C + (size_t)(row + 8) * N + col) = v1;
            }
        }
    }
}

// ---------------- beta/alpha projection ---------------------------------------
__global__ __launch_bounds__(128) void bgproj_k(const float* __restrict__ xn,
                                                const float* __restrict__ wb,
                                                const float* __restrict__ wg,
                                                float* __restrict__ ba)
{
    int m = blockIdx.x;
    int tid = threadIdx.x;
    float accb[8], accg[8];
    #pragma unroll
    for (int j = 0; j < 8; j++) { accb[j] = 0.f; accg[j] = 0.f; }

    const float* xr = xn + (size_t)m * D_ + tid*8;
    #pragma unroll
    for (int u = 0; u < 8; u++) {
        float xv = xr[u];
        int krow = tid*8 + u;
        const float4* wbp = (const float4*)(wb + (size_t)krow * H_);
        const float4* wgp = (const float4*)(wg + (size_t)krow * H_);
        float4 b0 = wbp[0], b1 = wbp[1];
        float4 g0 = wgp[0], g1 = wgp[1];
        accb[0] += xv*b0.x; accb[1] += xv*b0.y; accb[2] += xv*b0.z; accb[3] += xv*b0.w;
        accb[4] += xv*b1.x; accb[5] += xv*b1.y; accb[6] += xv*b1.z; accb[7] += xv*b1.w;
        accg[0] += xv*g0.x; accg[1] += xv*g0.y; accg[2] += xv*g0.z; accg[3] += xv*g0.w;
        accg[4] += xv*g1.x; accg[5] += xv*g1.y; accg[6] += xv*g1.z; accg[7] += xv*g1.w;
    }
    __shared__ float red[16][128];
    #pragma unroll
    for (int j = 0; j < 8; j++) { red[j][tid] = accb[j]; red[8+j][tid] = accg[j]; }
    __syncthreads();
    if (tid < 16) {
        float s = 0.f;
        for (int i = 0; i < 128; i++) s += red[tid][i];
        float val = sigmoid_f(s);
        int h = tid & 7;
        int which = tid >> 3;
        ba[((size_t)m * H_ + h)*2 + which] = val;
    }
}

// ---------------- gated DeltaNet recurrence -----------------------------------
// Reads fused qkv (stride 3072); writes o directly as fp16.
__global__ __launch_bounds__(128) void deltarec_k(const float* __restrict__ qkv,
                                                  const float* __restrict__ ba,
                                                  const float* __restrict__ s0,
                                                  __half* __restrict__ oh,
                                                  float* __restrict__ sout)
{
    int b = blockIdx.z, h = blockIdx.y, chunk = blockIdx.x;
    int tid = threadIdx.x;
    int warp = tid >> 5, lane = tid & 31;
    int grp = lane >> 4;
    int idx = lane & 15;
    int col = chunk*8 + warp*2 + grp;
    int r0  = idx * 8;

    float s[8];
    {
        const float* sp = s0 + (((size_t)(b*H_ + h)*DH_) + r0)*DH_ + col;
        #pragma unroll
        for (int i = 0; i < 8; i++) s[i] = sp[(size_t)i * DH_];
    }

    const float* base = qkv + (size_t)b * T_ * QKV_N + h * DH_;
    const float* qp  = base + r0;
    const float* kp  = base + 1024 + r0;
    const float* vp  = base + 2048 + col;
    const float* bap = ba + ((size_t)b * T_) * (H_*2) + h*2;
    size_t ooff = (size_t)b * T_ * D_ + (size_t)h * DH_ + col;

    float4 k0 = *(const float4*)(kp);
    float4 k1 = *(const float4*)(kp + 4);
    float4 q0 = *(const float4*)(qp);
    float4 q1 = *(const float4*)(qp + 4);
    float vv = *vp;
    float bb = bap[0];
    float aa = bap[1];

    for (int t = 0; t < T_; t++) {
        int tn = (t + 1 < T_) ? t + 1 : t;
        float4 nk0 = *(const float4*)(kp + (size_t)tn*QKV_N);
        float4 nk1 = *(const float4*)(kp + (size_t)tn*QKV_N + 4);
        float4 nq0 = *(const float4*)(qp + (size_t)tn*QKV_N);
        float4 nq1 = *(const float4*)(qp + (size_t)tn*QKV_N + 4);
        float nvv  = vp [(size_t)tn*QKV_N];
        float nbb  = bap[(size_t)tn*16];
        float naa  = bap[(size_t)tn*16 + 1];

        float kr[8] = {k0.x,k0.y,k0.z,k0.w,k1.x,k1.y,k1.z,k1.w};
        float qr[8] = {q0.x,q0.y,q0.z,q0.w,q1.x,q1.y,q1.z,q1.w};

        float pred = 0.f, po = 0.f, qk = 0.f;
        #pragma unroll
        for (int i = 0; i < 8; i++) {
            float sv = s[i] * aa;
            s[i] = sv;
            pred += kr[i] * sv;
            po   += qr[i] * sv;
            qk   += kr[i] * qr[i];
        }
        #pragma unroll
        for (int m = 1; m < 16; m <<= 1) {
            pred += __shfl_xor_sync(0xffffffffu, pred, m);
            po   += __shfl_xor_sync(0xffffffffu, po,   m);
            qk   += __shfl_xor_sync(0xffffffffu, qk,   m);
        }
        float dv = bb * (vv - pred);
        float ov = po + qk * dv;
        #pragma unroll
        for (int i = 0; i < 8; i++) s[i] += kr[i] * dv;

        if (idx == 0) oh[ooff + (size_t)t*D_] = __float2half(ov);

        k0 = nk0; k1 = nk1; q0 = nq0; q1 = nq1;
        vv = nvv; bb = nbb; aa = naa;
    }

    float* sp = sout + (((size_t)(b*H_ + h)*DH_) + r0)*DH_ + col;
    #pragma unroll
    for (int i = 0; i < 8; i++) sp[(size_t)i * DH_] = s[i];
}

// ---------------- launcher -----------------------------------------------------
struct Ptrs {
    float *xn, *qkv, *ba;
    __half *xh, *oh, *hh;
    __half *wqkv, *wo, *wgu, *wd;
    bool init = false;
};
static Ptrs P;

extern "C" void kernel_launch(void* const* d_in, const int* in_sizes, int n_in,
                              void* d_out, int out_size)
{
    const float* x   = (const float*)d_in[0];
    const float* st0 = (const float*)d_in[1];
    const float* wq  = (const float*)d_in[2];
    const float* wk  = (const float*)d_in[3];
    const float* wv  = (const float*)d_in[4];
    const float* wb  = (const float*)d_in[5];
    const float* wg  = (const float*)d_in[6];
    const float* wo  = (const float*)d_in[7];
    const float* wgate = (const float*)d_in[8];
    const float* wup   = (const float*)d_in[9];
    const float* wdown = (const float*)d_in[10];

    float* out = (float*)d_out;   // [x (4194304) | new_state (262144)]
    float* y   = out;
    float* stO = out + X_ELEMS;

    if (!P.init) {
        cudaGetSymbolAddress((void**)&P.xn,  g_xn);
        cudaGetSymbolAddress((void**)&P.qkv, g_qkv);
        cudaGetSymbolAddress((void**)&P.ba,  g_ba);
        cudaGetSymbolAddress((void**)&P.xh,  g_xh);
        cudaGetSymbolAddress((void**)&P.oh,  g_oh);
        cudaGetSymbolAddress((void**)&P.hh,  g_hh);
        cudaGetSymbolAddress((void**)&P.wqkv, g_wqkv);
        cudaGetSymbolAddress((void**)&P.wo,   g_wo);
        cudaGetSymbolAddress((void**)&P.wgu,  g_wgu);
        cudaGetSymbolAddress((void**)&P.wd,   g_wd);
        cudaFuncSetAttribute(hgemm_k<0>, cudaFuncAttributeMaxDynamicSharedMemorySize, HG_SMEM);
        cudaFuncSetAttribute(hgemm_k<1>, cudaFuncAttributeMaxDynamicSharedMemorySize, HG_SMEM);
        cudaFuncSetAttribute(hgemm_k<2>, cudaFuncAttributeMaxDynamicSharedMemorySize, HG_SMEM);
        P.init = true;
    }

    // [1] xn = rmsnorm(x) -> fp16 + fp32 (for bgproj)
    rmsnorm_h_k<<<M_, 256>>>(x, P.xh, P.xn);

    // [2-4] qkv weight transposes -> fp16 [N][K]
    tsplit_k<<<dim3(D_/32, D_/32), 256>>>(wq, P.wqkv, D_, D_, 1, 0);
    tsplit_k<<<dim3(D_/32, D_/32), 256>>>(wk, P.wqkv, D_, D_, 1, 1024);
    tsplit_k<<<dim3(D_/32, D_/32), 256>>>(wv, P.wqkv, D_, D_, 1, 2048);

    // [5] beta/alpha projection
    bgproj_k<<<M_, 128>>>(P.xn, wb, wg, P.ba);

    // [6] fused qkv projection   <-- ncu -s 5 -c 1 profiles THIS launch
    hgemm_k<0><<<dim3(QKV_N/128, M_/128), 128, HG_SMEM>>>(
        P.xh, P.wqkv, nullptr, P.qkv, nullptr, M_, QKV_N, D_);

    // [7] silu + per-head L2 norm (q,k); silu (v) — fused over qkv
    silul2_qkv_k<<<(M_*24)/8, 256>>>(P.qkv);

    // [8] recurrence -> o (fp16), final state
    deltarec_k<<<dim3(16, H_, B_), 128>>>(P.qkv, P.ba, st0, P.oh, stO);

    // [9] wo transpose; [10] y = x + o @ wo
    tsplit_k<<<dim3(D_/32, D_/32), 256>>>(wo, P.wo, D_, D_, 1, 0);
    hgemm_k<1><<<dim3(D_/128, M_/128), 128, HG_SMEM>>>(
        P.oh, P.wo, x, y, nullptr, M_, D_, D_);

    // [11] yn = rmsnorm(y) -> fp16
    rmsnorm_h_k<<<M_, 256>>>(y, P.xh, nullptr);

    // [12-13] gate/up transposes; [14] fused gate/up GEMM with swiglu epilogue
    tsplit_k<<<dim3(F_/32, D_/32), 256>>>(wgate, P.wgu, D_, F_, 2, 0);
    tsplit_k<<<dim3(F_/32, D_/32), 256>>>(wup,   P.wgu, D_, F_, 2, 1);
    hgemm_k<2><<<dim3(2*F_/128, M_/128), 128, HG_SMEM>>>(
        P.xh, P.wgu, nullptr, nullptr, P.hh, M_, 2*F_, D_);

    // [15] wdown transpose; [16] out = y + h @ w_down
    tsplit_k<<<dim3(D_/32, F_/32), 256>>>(wdown, P.wd, F_, D_, 1, 0);
    hgemm_k<1><<<dim3(D_/128, M_/128), 128, HG_SMEM>>>(
        P.hh, P.wd, y, y, nullptr, M_, D_, F_);
}